// round 1
// baseline (speedup 1.0000x reference)
#include <cuda_runtime.h>
#include <math.h>
#include <stdint.h>

// ---------------- problem constants ----------------
#define LN_   12
#define HN_   12
#define DM_   768
#define TM_   1024
#define BN_   4
#define VN_   50257
#define DH_   64
#define MR_   (BN_*TM_)     // 4096 rows
#define FF_   (4*DM_)       // 3072

// ---------------- scratch (device globals; no allocs) ----------------
__device__ float g_x [MR_*DM_];
__device__ float g_h [MR_*DM_];
__device__ float g_q [MR_*DM_];
__device__ float g_k [MR_*DM_];
__device__ float g_v [MR_*DM_];
__device__ float g_y [MR_*DM_];
__device__ float g_fc[MR_*FF_];

// ---------------- embedding ----------------
__global__ void embed_kernel(const int* __restrict__ idx,
                             const float* __restrict__ wte,
                             const float* __restrict__ wpe,
                             float* __restrict__ x) {
    int row = blockIdx.x;             // 0..MR_-1, row = b*T + t
    int t   = row & (TM_ - 1);
    int tok = idx[row];
    const float* we = wte + (size_t)tok * DM_;
    const float* pe = wpe + (size_t)t   * DM_;
    float* xr = x + (size_t)row * DM_;
    for (int d = threadIdx.x; d < DM_; d += blockDim.x)
        xr[d] = we[d] + pe[d];
}

// ---------------- layernorm (one block per row) ----------------
__global__ void ln_kernel(const float* __restrict__ x,
                          const float* __restrict__ w,
                          const float* __restrict__ b,
                          float* __restrict__ out) {
    int row = blockIdx.x;
    const float* xr = x + (size_t)row * DM_;
    float s = 0.f, sq = 0.f;
    for (int d = threadIdx.x; d < DM_; d += blockDim.x) {
        float v = xr[d];
        s += v; sq += v * v;
    }
    __shared__ float sh_s[8], sh_q[8];
    #pragma unroll
    for (int o = 16; o; o >>= 1) {
        s  += __shfl_xor_sync(0xffffffffu, s,  o);
        sq += __shfl_xor_sync(0xffffffffu, sq, o);
    }
    int wid = threadIdx.x >> 5, lane = threadIdx.x & 31;
    if (lane == 0) { sh_s[wid] = s; sh_q[wid] = sq; }
    __syncthreads();
    s = 0.f; sq = 0.f;
    #pragma unroll
    for (int i = 0; i < 8; i++) { s += sh_s[i]; sq += sh_q[i]; }
    float mean = s * (1.0f / DM_);
    float var  = sq * (1.0f / DM_) - mean * mean;
    float rstd = rsqrtf(var + 1e-5f);
    float* orow = out + (size_t)row * DM_;
    for (int d = threadIdx.x; d < DM_; d += blockDim.x)
        orow[d] = (xr[d] - mean) * rstd * w[d] + b[d];
}

// ---------------- SGEMM: C[M,N] = A[M,K] @ B[K,N] (+epilogue) ----------------
// EPI: 0 = +bias, 1 = +bias +residual, 2 = +bias then gelu(tanh), 3 = none
// Requires M % 128 == 0 and K % 8 == 0 (true for all call sites).
template<int EPI>
__global__ void __launch_bounds__(256)
sgemm_kernel(const float* __restrict__ A, const float* __restrict__ Bw,
             const float* __restrict__ bias, const float* __restrict__ res,
             float* __restrict__ C, int M, int N, int K) {
    __shared__ float As[8][128];
    __shared__ float Bs[8][132];   // pad to avoid conflicts on strided writes

    const int tid = threadIdx.x;
    const int m0 = blockIdx.y * 128;
    const int n0 = blockIdx.x * 128;

    const int aRow = tid >> 1;          // 0..127
    const int aCol = (tid & 1) * 4;     // 0 or 4
    const int bRow = tid >> 5;          // 0..7
    const int bCol = (tid & 31) * 4;    // 0..124

    const int tx = tid & 15;            // col group
    const int ty = tid >> 4;            // row group

    float acc[8][8];
    #pragma unroll
    for (int i = 0; i < 8; i++)
        #pragma unroll
        for (int j = 0; j < 8; j++) acc[i][j] = 0.f;

    const float* Aptr = A + (size_t)(m0 + aRow) * K + aCol;

    for (int k0 = 0; k0 < K; k0 += 8) {
        // A tile (float4, always in bounds)
        float4 av = *reinterpret_cast<const float4*>(Aptr + k0);
        As[aCol + 0][aRow] = av.x;
        As[aCol + 1][aRow] = av.y;
        As[aCol + 2][aRow] = av.z;
        As[aCol + 3][aRow] = av.w;
        // B tile (scalar, N-guarded)
        const float* brow = Bw + (size_t)(k0 + bRow) * N;
        #pragma unroll
        for (int j = 0; j < 4; j++) {
            int n = n0 + bCol + j;
            Bs[bRow][bCol + j] = (n < N) ? brow[n] : 0.f;
        }
        __syncthreads();

        #pragma unroll
        for (int k = 0; k < 8; k++) {
            float a[8], bb[8];
            #pragma unroll
            for (int i = 0; i < 8; i++) a[i]  = As[k][ty * 8 + i];
            #pragma unroll
            for (int j = 0; j < 8; j++) bb[j] = Bs[k][tx * 8 + j];
            #pragma unroll
            for (int i = 0; i < 8; i++)
                #pragma unroll
                for (int j = 0; j < 8; j++)
                    acc[i][j] += a[i] * bb[j];
        }
        __syncthreads();
    }

    const float kgelu = 0.7978845608028654f;
    #pragma unroll
    for (int i = 0; i < 8; i++) {
        int row = m0 + ty * 8 + i;
        float* crow = C + (size_t)row * N;
        const float* rrow = (EPI == 1) ? (res + (size_t)row * N) : nullptr;
        #pragma unroll
        for (int j = 0; j < 8; j++) {
            int col = n0 + tx * 8 + j;
            if (col < N) {
                float val = acc[i][j];
                if (EPI != 3) val += bias[col];
                if (EPI == 1) val += rrow[col];
                if (EPI == 2) {
                    float u = kgelu * (val + 0.044715f * val * val * val);
                    val = 0.5f * val * (1.0f + tanhf(u));
                }
                crow[col] = val;
            }
        }
    }
}

// ---------------- attention: one warp per query, online softmax ----------------
__global__ void attn_kernel(const float* __restrict__ q,
                            const float* __restrict__ k,
                            const float* __restrict__ v,
                            float* __restrict__ y) {
    int gw   = (blockIdx.x * blockDim.x + threadIdx.x) >> 5;  // global warp id
    int lane = threadIdx.x & 31;
    int qi = gw & (TM_ - 1);
    int bh = gw >> 10;                 // TM_ = 1024
    int h  = bh % HN_;
    int b  = bh / HN_;

    const float* qp = q + ((size_t)(b * TM_ + qi) * DM_ + h * DH_);
    float q0 = qp[lane], q1 = qp[lane + 32];

    const float scale = 0.125f;  // 1/sqrt(64)
    float m = -1e30f, s = 0.f, a0 = 0.f, a1 = 0.f;

    const float* kbase = k + (size_t)b * TM_ * DM_ + h * DH_;
    const float* vbase = v + (size_t)b * TM_ * DM_ + h * DH_;

    for (int kk = 0; kk <= qi; kk++) {
        const float* kp = kbase + (size_t)kk * DM_;
        float d = q0 * kp[lane] + q1 * kp[lane + 32];
        #pragma unroll
        for (int o = 16; o; o >>= 1) d += __shfl_xor_sync(0xffffffffu, d, o);
        d *= scale;
        float mn = fmaxf(m, d);
        float f  = __expf(m - mn);
        float p  = __expf(d - mn);
        const float* vp = vbase + (size_t)kk * DM_;
        s  = s  * f + p;
        a0 = a0 * f + p * vp[lane];
        a1 = a1 * f + p * vp[lane + 32];
        m = mn;
    }
    float inv = 1.0f / s;
    float* yp = y + ((size_t)(b * TM_ + qi) * DM_ + h * DH_);
    yp[lane]      = a0 * inv;
    yp[lane + 32] = a1 * inv;
}

// ---------------- launch ----------------
extern "C" void kernel_launch(void* const* d_in, const int* in_sizes, int n_in,
                              void* d_out, int out_size) {
    const int*   idx  = (const int*)  d_in[0];
    const float* wte  = (const float*)d_in[1];
    const float* wpe  = (const float*)d_in[2];
    const float* ln1w = (const float*)d_in[3];
    const float* ln1b = (const float*)d_in[4];
    const float* Wq   = (const float*)d_in[5];
    const float* bq   = (const float*)d_in[6];
    const float* Wk   = (const float*)d_in[7];
    const float* bk   = (const float*)d_in[8];
    const float* Wv   = (const float*)d_in[9];
    const float* bv   = (const float*)d_in[10];
    const float* Wo   = (const float*)d_in[11];
    const float* bo   = (const float*)d_in[12];
    const float* ln2w = (const float*)d_in[13];
    const float* ln2b = (const float*)d_in[14];
    const float* Wfc  = (const float*)d_in[15];
    const float* bfc  = (const float*)d_in[16];
    const float* Wpr  = (const float*)d_in[17];
    const float* bpr  = (const float*)d_in[18];
    const float* lnfw = (const float*)d_in[19];
    const float* lnfb = (const float*)d_in[20];
    const float* Wlm  = (const float*)d_in[21];
    float* out = (float*)d_out;

    float *x, *h, *qb, *kb, *vb, *yb, *fcb;
    cudaGetSymbolAddress((void**)&x,   g_x);
    cudaGetSymbolAddress((void**)&h,   g_h);
    cudaGetSymbolAddress((void**)&qb,  g_q);
    cudaGetSymbolAddress((void**)&kb,  g_k);
    cudaGetSymbolAddress((void**)&vb,  g_v);
    cudaGetSymbolAddress((void**)&yb,  g_y);
    cudaGetSymbolAddress((void**)&fcb, g_fc);

    embed_kernel<<<MR_, 256>>>(idx, wte, wpe, x);

    dim3 g768 (DM_ / 128, MR_ / 128);          // 6 x 32
    dim3 g3072(FF_ / 128, MR_ / 128);          // 24 x 32
    dim3 glm  ((VN_ + 127) / 128, MR_ / 128);  // 393 x 32

    for (int l = 0; l < LN_; l++) {
        const size_t wdd = (size_t)l * DM_ * DM_;
        const size_t wff = (size_t)l * DM_ * FF_;

        ln_kernel<<<MR_, 256>>>(x, ln1w + l * DM_, ln1b + l * DM_, h);

        sgemm_kernel<0><<<g768, 256>>>(h, Wq + wdd, bq + l * DM_, nullptr, qb, MR_, DM_, DM_);
        sgemm_kernel<0><<<g768, 256>>>(h, Wk + wdd, bk + l * DM_, nullptr, kb, MR_, DM_, DM_);
        sgemm_kernel<0><<<g768, 256>>>(h, Wv + wdd, bv + l * DM_, nullptr, vb, MR_, DM_, DM_);

        attn_kernel<<<(BN_ * HN_ * TM_) / 4, 128>>>(qb, kb, vb, yb);

        sgemm_kernel<1><<<g768, 256>>>(yb, Wo + wdd, bo + l * DM_, x, x, MR_, DM_, DM_);

        ln_kernel<<<MR_, 256>>>(x, ln2w + l * DM_, ln2b + l * DM_, h);

        sgemm_kernel<2><<<g3072, 256>>>(h, Wfc + wff, bfc + (size_t)l * FF_, nullptr, fcb,
                                        MR_, FF_, DM_);
        sgemm_kernel<1><<<g768, 256>>>(fcb, Wpr + wff, bpr + l * DM_, x, x,
                                       MR_, DM_, FF_);
    }

    ln_kernel<<<MR_, 256>>>(x, lnfw, lnfb, h);
    sgemm_kernel<3><<<glm, 256>>>(h, Wlm, nullptr, nullptr, out, MR_, VN_, DM_);
}

// round 2
// speedup vs baseline: 1.0013x; 1.0013x over previous
#include <cuda_runtime.h>
#include <math.h>
#include <stdint.h>

// ---------------- problem constants ----------------
#define LN_   12
#define HN_   12
#define DM_   768
#define TM_   1024
#define BN_   4
#define VN_   50257
#define DH_   64
#define MR_   (BN_*TM_)     // 4096 rows
#define FF_   (4*DM_)       // 3072

// ---------------- scratch (device globals; no allocs) ----------------
__device__ float g_x [MR_*DM_];
__device__ float g_h [MR_*DM_];
__device__ float g_q [MR_*DM_];
__device__ float g_k [MR_*DM_];
__device__ float g_v [MR_*DM_];
__device__ float g_y [MR_*DM_];
__device__ float g_fc[MR_*FF_];

// ---------------- embedding ----------------
__global__ void embed_kernel(const int* __restrict__ idx,
                             const float* __restrict__ wte,
                             const float* __restrict__ wpe,
                             float* __restrict__ x) {
    int row = blockIdx.x;             // 0..MR_-1, row = b*T + t
    int t   = row & (TM_ - 1);
    int tok = idx[row];
    const float* we = wte + (size_t)tok * DM_;
    const float* pe = wpe + (size_t)t   * DM_;
    float* xr = x + (size_t)row * DM_;
    for (int d = threadIdx.x; d < DM_; d += blockDim.x)
        xr[d] = we[d] + pe[d];
}

// ---------------- layernorm (one block per row) ----------------
__global__ void ln_kernel(const float* __restrict__ x,
                          const float* __restrict__ w,
                          const float* __restrict__ b,
                          float* __restrict__ out) {
    int row = blockIdx.x;
    const float* xr = x + (size_t)row * DM_;
    float s = 0.f, sq = 0.f;
    for (int d = threadIdx.x; d < DM_; d += blockDim.x) {
        float v = xr[d];
        s += v; sq += v * v;
    }
    __shared__ float sh_s[8], sh_q[8];
    #pragma unroll
    for (int o = 16; o; o >>= 1) {
        s  += __shfl_xor_sync(0xffffffffu, s,  o);
        sq += __shfl_xor_sync(0xffffffffu, sq, o);
    }
    int wid = threadIdx.x >> 5, lane = threadIdx.x & 31;
    if (lane == 0) { sh_s[wid] = s; sh_q[wid] = sq; }
    __syncthreads();
    s = 0.f; sq = 0.f;
    #pragma unroll
    for (int i = 0; i < 8; i++) { s += sh_s[i]; sq += sh_q[i]; }
    float mean = s * (1.0f / DM_);
    float var  = sq * (1.0f / DM_) - mean * mean;
    float rstd = rsqrtf(var + 1e-5f);
    float* orow = out + (size_t)row * DM_;
    for (int d = threadIdx.x; d < DM_; d += blockDim.x)
        orow[d] = (xr[d] - mean) * rstd * w[d] + b[d];
}

// ---------------- SGEMM: C[M,N] = A[M,K] @ B[K,N] (+epilogue) ----------------
// EPI: 0 = +bias, 1 = +bias +residual, 2 = +bias then gelu(tanh), 3 = none
// Requires M % 128 == 0 and K % 8 == 0 (true for all call sites).
template<int EPI>
__global__ void __launch_bounds__(256)
sgemm_kernel(const float* __restrict__ A, const float* __restrict__ Bw,
             const float* __restrict__ bias, const float* __restrict__ res,
             float* __restrict__ C, int M, int N, int K) {
    __shared__ float As[8][128];
    __shared__ float Bs[8][132];   // pad to avoid conflicts on strided writes

    const int tid = threadIdx.x;
    const int m0 = blockIdx.y * 128;
    const int n0 = blockIdx.x * 128;

    const int aRow = tid >> 1;          // 0..127
    const int aCol = (tid & 1) * 4;     // 0 or 4
    const int bRow = tid >> 5;          // 0..7
    const int bCol = (tid & 31) * 4;    // 0..124

    const int tx = tid & 15;            // col group
    const int ty = tid >> 4;            // row group

    float acc[8][8];
    #pragma unroll
    for (int i = 0; i < 8; i++)
        #pragma unroll
        for (int j = 0; j < 8; j++) acc[i][j] = 0.f;

    const float* Aptr = A + (size_t)(m0 + aRow) * K + aCol;

    for (int k0 = 0; k0 < K; k0 += 8) {
        // A tile (float4, always in bounds)
        float4 av = *reinterpret_cast<const float4*>(Aptr + k0);
        As[aCol + 0][aRow] = av.x;
        As[aCol + 1][aRow] = av.y;
        As[aCol + 2][aRow] = av.z;
        As[aCol + 3][aRow] = av.w;
        // B tile (scalar, N-guarded)
        const float* brow = Bw + (size_t)(k0 + bRow) * N;
        #pragma unroll
        for (int j = 0; j < 4; j++) {
            int n = n0 + bCol + j;
            Bs[bRow][bCol + j] = (n < N) ? brow[n] : 0.f;
        }
        __syncthreads();

        #pragma unroll
        for (int k = 0; k < 8; k++) {
            float a[8], bb[8];
            #pragma unroll
            for (int i = 0; i < 8; i++) a[i]  = As[k][ty * 8 + i];
            #pragma unroll
            for (int j = 0; j < 8; j++) bb[j] = Bs[k][tx * 8 + j];
            #pragma unroll
            for (int i = 0; i < 8; i++)
                #pragma unroll
                for (int j = 0; j < 8; j++)
                    acc[i][j] += a[i] * bb[j];
        }
        __syncthreads();
    }

    const float kgelu = 0.7978845608028654f;
    #pragma unroll
    for (int i = 0; i < 8; i++) {
        int row = m0 + ty * 8 + i;
        float* crow = C + (size_t)row * N;
        const float* rrow = (EPI == 1) ? (res + (size_t)row * N) : nullptr;
        #pragma unroll
        for (int j = 0; j < 8; j++) {
            int col = n0 + tx * 8 + j;
            if (col < N) {
                float val = acc[i][j];
                if (EPI != 3) val += bias[col];
                if (EPI == 1) val += rrow[col];
                if (EPI == 2) {
                    float u = kgelu * (val + 0.044715f * val * val * val);
                    val = 0.5f * val * (1.0f + tanhf(u));
                }
                crow[col] = val;
            }
        }
    }
}

// ---------------- attention: one warp per query, online softmax ----------------
__global__ void attn_kernel(const float* __restrict__ q,
                            const float* __restrict__ k,
                            const float* __restrict__ v,
                            float* __restrict__ y) {
    int gw   = (blockIdx.x * blockDim.x + threadIdx.x) >> 5;  // global warp id
    int lane = threadIdx.x & 31;
    int qi = gw & (TM_ - 1);
    int bh = gw >> 10;                 // TM_ = 1024
    int h  = bh % HN_;
    int b  = bh / HN_;

    const float* qp = q + ((size_t)(b * TM_ + qi) * DM_ + h * DH_);
    float q0 = qp[lane], q1 = qp[lane + 32];

    const float scale = 0.125f;  // 1/sqrt(64)
    float m = -1e30f, s = 0.f, a0 = 0.f, a1 = 0.f;

    const float* kbase = k + (size_t)b * TM_ * DM_ + h * DH_;
    const float* vbase = v + (size_t)b * TM_ * DM_ + h * DH_;

    for (int kk = 0; kk <= qi; kk++) {
        const float* kp = kbase + (size_t)kk * DM_;
        float d = q0 * kp[lane] + q1 * kp[lane + 32];
        #pragma unroll
        for (int o = 16; o; o >>= 1) d += __shfl_xor_sync(0xffffffffu, d, o);
        d *= scale;
        float mn = fmaxf(m, d);
        float f  = __expf(m - mn);
        float p  = __expf(d - mn);
        const float* vp = vbase + (size_t)kk * DM_;
        s  = s  * f + p;
        a0 = a0 * f + p * vp[lane];
        a1 = a1 * f + p * vp[lane + 32];
        m = mn;
    }
    float inv = 1.0f / s;
    float* yp = y + ((size_t)(b * TM_ + qi) * DM_ + h * DH_);
    yp[lane]      = a0 * inv;
    yp[lane + 32] = a1 * inv;
}

// ---------------- launch ----------------
extern "C" void kernel_launch(void* const* d_in, const int* in_sizes, int n_in,
                              void* d_out, int out_size) {
    const int*   idx  = (const int*)  d_in[0];
    const float* wte  = (const float*)d_in[1];
    const float* wpe  = (const float*)d_in[2];
    const float* ln1w = (const float*)d_in[3];
    const float* ln1b = (const float*)d_in[4];
    const float* Wq   = (const float*)d_in[5];
    const float* bq   = (const float*)d_in[6];
    const float* Wk   = (const float*)d_in[7];
    const float* bk   = (const float*)d_in[8];
    const float* Wv   = (const float*)d_in[9];
    const float* bv   = (const float*)d_in[10];
    const float* Wo   = (const float*)d_in[11];
    const float* bo   = (const float*)d_in[12];
    const float* ln2w = (const float*)d_in[13];
    const float* ln2b = (const float*)d_in[14];
    const float* Wfc  = (const float*)d_in[15];
    const float* bfc  = (const float*)d_in[16];
    const float* Wpr  = (const float*)d_in[17];
    const float* bpr  = (const float*)d_in[18];
    const float* lnfw = (const float*)d_in[19];
    const float* lnfb = (const float*)d_in[20];
    const float* Wlm  = (const float*)d_in[21];
    float* out = (float*)d_out;

    float *x, *h, *qb, *kb, *vb, *yb, *fcb;
    cudaGetSymbolAddress((void**)&x,   g_x);
    cudaGetSymbolAddress((void**)&h,   g_h);
    cudaGetSymbolAddress((void**)&qb,  g_q);
    cudaGetSymbolAddress((void**)&kb,  g_k);
    cudaGetSymbolAddress((void**)&vb,  g_v);
    cudaGetSymbolAddress((void**)&yb,  g_y);
    cudaGetSymbolAddress((void**)&fcb, g_fc);

    embed_kernel<<<MR_, 256>>>(idx, wte, wpe, x);

    dim3 g768 (DM_ / 128, MR_ / 128);          // 6 x 32
    dim3 g3072(FF_ / 128, MR_ / 128);          // 24 x 32
    dim3 glm  ((VN_ + 127) / 128, MR_ / 128);  // 393 x 32

    for (int l = 0; l < LN_; l++) {
        const size_t wdd = (size_t)l * DM_ * DM_;
        const size_t wff = (size_t)l * DM_ * FF_;

        ln_kernel<<<MR_, 256>>>(x, ln1w + l * DM_, ln1b + l * DM_, h);

        sgemm_kernel<0><<<g768, 256>>>(h, Wq + wdd, bq + l * DM_, nullptr, qb, MR_, DM_, DM_);
        sgemm_kernel<0><<<g768, 256>>>(h, Wk + wdd, bk + l * DM_, nullptr, kb, MR_, DM_, DM_);
        sgemm_kernel<0><<<g768, 256>>>(h, Wv + wdd, bv + l * DM_, nullptr, vb, MR_, DM_, DM_);

        attn_kernel<<<(BN_ * HN_ * TM_) / 4, 128>>>(qb, kb, vb, yb);

        sgemm_kernel<1><<<g768, 256>>>(yb, Wo + wdd, bo + l * DM_, x, x, MR_, DM_, DM_);

        ln_kernel<<<MR_, 256>>>(x, ln2w + l * DM_, ln2b + l * DM_, h);

        sgemm_kernel<2><<<g3072, 256>>>(h, Wfc + wff, bfc + (size_t)l * FF_, nullptr, fcb,
                                        MR_, FF_, DM_);
        sgemm_kernel<1><<<g768, 256>>>(fcb, Wpr + wff, bpr + l * DM_, x, x,
                                       MR_, DM_, FF_);
    }

    ln_kernel<<<MR_, 256>>>(x, lnfw, lnfb, h);
    sgemm_kernel<3><<<glm, 256>>>(h, Wlm, nullptr, nullptr, out, MR_, VN_, DM_);
}

// round 5
// speedup vs baseline: 2.3182x; 2.3151x over previous
#include <cuda_runtime.h>
#include <cuda_bf16.h>
#include <math.h>
#include <stdint.h>

#define LN_ 12
#define HN_ 12
#define DM_ 768
#define TM_ 1024
#define BN_ 4
#define VN_ 50257
#define DH_ 64
#define MR_ (BN_*TM_)
#define FF_ (4*DM_)

typedef __nv_bfloat16 bf16;

// ---------------- scratch ----------------
__device__ float g_x [MR_*DM_];
__device__ float g_qf[MR_*DM_];
__device__ float g_kf[MR_*DM_];
__device__ float g_vf[MR_*DM_];
__device__ bf16 g_hh[MR_*DM_], g_hl[MR_*DM_];
__device__ bf16 g_yh[MR_*DM_], g_yl[MR_*DM_];
__device__ bf16 g_fh[MR_*FF_], g_fl[MR_*FF_];
__device__ bf16 g_Wqh[LN_*DM_*DM_], g_Wql[LN_*DM_*DM_];
__device__ bf16 g_Wkh[LN_*DM_*DM_], g_Wkl[LN_*DM_*DM_];
__device__ bf16 g_Wvh[LN_*DM_*DM_], g_Wvl[LN_*DM_*DM_];
__device__ bf16 g_Woh[LN_*DM_*DM_], g_Wol[LN_*DM_*DM_];
__device__ bf16 g_Wfh[LN_*DM_*FF_], g_Wfl[LN_*DM_*FF_];
__device__ bf16 g_Wph[LN_*DM_*FF_], g_Wpl[LN_*DM_*FF_];
__device__ bf16 g_Wlh[(size_t)VN_*DM_], g_Wll[(size_t)VN_*DM_];

// ---------------- PTX helpers (base sm_103 target only!) ----------------
__device__ __forceinline__ uint32_t su32(const void* p){
    uint32_t a; asm("{ .reg .u64 t; cvta.to.shared.u64 t, %1; cvt.u32.u64 %0, t; }":"=r"(a):"l"(p)); return a;
}
__device__ __forceinline__ void mma16816(float* c, const uint32_t* a, const uint32_t* b){
    asm volatile("mma.sync.aligned.m16n8k16.row.col.f32.bf16.bf16.f32 "
        "{%0,%1,%2,%3},{%4,%5,%6,%7},{%8,%9},{%0,%1,%2,%3};"
        : "+f"(c[0]),"+f"(c[1]),"+f"(c[2]),"+f"(c[3])
        : "r"(a[0]),"r"(a[1]),"r"(a[2]),"r"(a[3]),"r"(b[0]),"r"(b[1]));
}
__device__ __forceinline__ void ldsm4(uint32_t* r, uint32_t a){
    asm volatile("ldmatrix.sync.aligned.m8n8.x4.shared.b16 {%0,%1,%2,%3},[%4];"
        :"=r"(r[0]),"=r"(r[1]),"=r"(r[2]),"=r"(r[3]):"r"(a));
}
__device__ __forceinline__ void cpa(uint32_t d, const void* g, int vb){
    asm volatile("cp.async.cg.shared.global [%0],[%1],16,%2;"::"r"(d),"l"(g),"r"(vb):"memory");
}
__device__ __forceinline__ void cpcommit(){ asm volatile("cp.async.commit_group;":::"memory"); }
template<int N> __device__ __forceinline__ void cpwait(){ asm volatile("cp.async.wait_group %0;"::"n"(N):"memory"); }

// ---------------- weight transpose + split: W[K,N] -> [N,K] hi/lo ----------------
__global__ void wconv_kernel(const float* __restrict__ W, bf16* __restrict__ oh, bf16* __restrict__ ol,
                             int K, int N){
    __shared__ float t[32][33];
    int l = blockIdx.z;
    W  += (size_t)l*K*N; oh += (size_t)l*K*N; ol += (size_t)l*K*N;
    int k0 = blockIdx.y*32, n0 = blockIdx.x*32;
    #pragma unroll
    for (int i=0;i<4;i++){
        int k = k0 + threadIdx.y + i*8, n = n0 + threadIdx.x;
        t[threadIdx.y+i*8][threadIdx.x] = (n<N) ? W[(size_t)k*N+n] : 0.f;
    }
    __syncthreads();
    #pragma unroll
    for (int i=0;i<4;i++){
        int n = n0 + threadIdx.y + i*8, k = k0 + threadIdx.x;
        if (n<N){
            float v = t[threadIdx.x][threadIdx.y+i*8];
            bf16 h = __float2bfloat16(v);
            oh[(size_t)n*K+k] = h;
            ol[(size_t)n*K+k] = __float2bfloat16(v - __bfloat162float(h));
        }
    }
}

// ---------------- embedding ----------------
__global__ void embed_kernel(const int* __restrict__ idx, const float* __restrict__ wte,
                             const float* __restrict__ wpe, float* __restrict__ x){
    int row = blockIdx.x;
    float4 a = ((const float4*)(wte + (size_t)idx[row]*DM_))[threadIdx.x];
    float4 p = ((const float4*)(wpe + (size_t)(row&(TM_-1))*DM_))[threadIdx.x];
    a.x+=p.x; a.y+=p.y; a.z+=p.z; a.w+=p.w;
    ((float4*)(x + (size_t)row*DM_))[threadIdx.x] = a;
}

// ---------------- layernorm -> bf16 hi/lo (192 threads) ----------------
__global__ void ln_kernel(const float* __restrict__ x, const float* __restrict__ w, const float* __restrict__ b,
                          bf16* __restrict__ oh, bf16* __restrict__ ol){
    int row = blockIdx.x, tid = threadIdx.x;
    float4 v = ((const float4*)(x + (size_t)row*DM_))[tid];
    float s = v.x+v.y+v.z+v.w;
    float sq = v.x*v.x+v.y*v.y+v.z*v.z+v.w*v.w;
    __shared__ float ss[6], sp[6];
    #pragma unroll
    for (int o=16;o;o>>=1){ s+=__shfl_xor_sync(~0u,s,o); sq+=__shfl_xor_sync(~0u,sq,o); }
    if ((tid&31)==0){ ss[tid>>5]=s; sp[tid>>5]=sq; }
    __syncthreads();
    s=0; sq=0;
    #pragma unroll
    for (int i=0;i<6;i++){ s+=ss[i]; sq+=sp[i]; }
    float mean = s*(1.f/DM_), var = sq*(1.f/DM_)-mean*mean, rstd = rsqrtf(var+1e-5f);
    float4 wv = ((const float4*)w)[tid], bv = ((const float4*)b)[tid];
    float y[4] = {(v.x-mean)*rstd*wv.x+bv.x, (v.y-mean)*rstd*wv.y+bv.y,
                  (v.z-mean)*rstd*wv.z+bv.z, (v.w-mean)*rstd*wv.w+bv.w};
    bf16 hh[4], ll[4];
    #pragma unroll
    for (int i=0;i<4;i++){ hh[i]=__float2bfloat16(y[i]); ll[i]=__float2bfloat16(y[i]-__bfloat162float(hh[i])); }
    ((uint2*)(oh + (size_t)row*DM_))[tid] = *(uint2*)hh;
    ((uint2*)(ol + (size_t)row*DM_))[tid] = *(uint2*)ll;
}

// ---------------- HMMA GEMM: C[M,N] = (Ah+Al)[M,K] @ (Bh+Bl)[N,K]^T ----------------
// EPI: 0 bias->f32, 1 bias+res->f32, 2 bias+gelu->bf16 split, 3 none->f32
// Tiles: CTA 128x128x32, 3-stage cp.async, 8 warps (2m x 4n), warp 64x32.
#define TILE_  10240          // 128 rows * 80B (32 bf16 + 8 pad)
#define STG_   (4*TILE_)      // Ah | Al | Bh | Bl
#define TGSMEM (3*STG_)       // 3 stages = 122880 B
template<int EPI>
__global__ void __launch_bounds__(256)
tgemm(const bf16* __restrict__ Ah, const bf16* __restrict__ Al,
      const bf16* __restrict__ Bh, const bf16* __restrict__ Bl,
      const float* __restrict__ bias, const float* __restrict__ res,
      float* __restrict__ outf, bf16* __restrict__ outh, bf16* __restrict__ outl,
      int N, int K){
    extern __shared__ char smem[];
    uint32_t sb = su32(smem);
    const int tid = threadIdx.x;
    const int m0 = blockIdx.y*128, n0 = blockIdx.x*128;
    const int NT = K >> 5;
    const bf16* srcs[4] = {Ah, Al, Bh, Bl};

    auto load_tile = [&](int kt){
        uint32_t base = sb + (uint32_t)(kt%3)*STG_;
        #pragma unroll
        for (int t=0;t<4;t++){
            const bf16* src = srcs[t];
            int row0 = (t<2)? m0 : n0;
            uint32_t tb = base + (uint32_t)t*TILE_;
            #pragma unroll
            for (int i=0;i<2;i++){
                int id = tid + i*256;
                int r = id>>2, c = id&3;
                const char* g = (const char*)(src + (size_t)(row0+r)*K + kt*32) + c*16;
                int vb = (t>=2 && (row0+r)>=N) ? 0 : 16;
                cpa(tb + (uint32_t)(r*80 + c*16), g, vb);
            }
        }
        cpcommit();
    };

    load_tile(0); load_tile(1); load_tile(2);

    const int l = tid & 31;
    const int wid = tid >> 5, wm = wid & 1, wn = wid >> 1;
    // ldmatrix per-thread offsets (bytes)
    const uint32_t aoff = (uint32_t)((wm*64 + (l&7) + ((l>>3)&1)*8)*80 + (l>>4)*16);
    const uint32_t boff = (uint32_t)((wn*32 + (l&7) + (l>>4)*8)*80 + ((l>>3)&1)*16);

    float acc[4][4][4];
    #pragma unroll
    for (int i=0;i<4;i++) for (int j=0;j<4;j++) for (int r=0;r<4;r++) acc[i][j][r]=0.f;

    for (int kt=0; kt<NT; kt++){
        if (kt+3<=NT) cpwait<2>();
        else if (kt+2==NT) cpwait<1>();
        else cpwait<0>();
        __syncthreads();
        uint32_t base = sb + (uint32_t)(kt%3)*STG_;
        #pragma unroll
        for (int ks=0; ks<2; ks++){
            uint32_t ah[4][4], al_[4][4], bh[2][4], bl[2][4];
            #pragma unroll
            for (int mi=0; mi<4; mi++){
                ldsm4(ah[mi],  base          + aoff + (uint32_t)(mi*16*80 + ks*32));
                ldsm4(al_[mi], base + TILE_  + aoff + (uint32_t)(mi*16*80 + ks*32));
            }
            #pragma unroll
            for (int nb=0; nb<2; nb++){
                ldsm4(bh[nb], base + 2*TILE_ + boff + (uint32_t)(nb*16*80 + ks*32));
                ldsm4(bl[nb], base + 3*TILE_ + boff + (uint32_t)(nb*16*80 + ks*32));
            }
            #pragma unroll
            for (int mi=0; mi<4; mi++){
                #pragma unroll
                for (int ni=0; ni<4; ni++){
                    const uint32_t* bhp = &bh[ni>>1][(ni&1)*2];
                    const uint32_t* blp = &bl[ni>>1][(ni&1)*2];
                    mma16816(acc[mi][ni], ah[mi],  bhp);
                    mma16816(acc[mi][ni], al_[mi], bhp);
                    mma16816(acc[mi][ni], ah[mi],  blp);
                }
            }
        }
        __syncthreads();
        if (kt+3<NT) load_tile(kt+3);
    }

    // epilogue: direct global writes
    const float kg = 0.7978845608028654f;
    #pragma unroll
    for (int mi=0; mi<4; mi++){
        #pragma unroll
        for (int ni=0; ni<4; ni++){
            #pragma unroll
            for (int half=0; half<2; half++){
                int r = m0 + wm*64 + mi*16 + (l>>2) + half*8;
                int c = n0 + wn*32 + ni*8 + (l&3)*2;
                float v0 = acc[mi][ni][half*2], v1 = acc[mi][ni][half*2+1];
                #pragma unroll
                for (int e=0; e<2; e++){
                    int cc = c + e;
                    if (cc < N){
                        float v = e ? v1 : v0;
                        size_t o = (size_t)r*N + cc;
                        if (EPI==0) outf[o] = v + bias[cc];
                        else if (EPI==1) outf[o] = v + bias[cc] + res[o];
                        else if (EPI==2){
                            v += bias[cc];
                            float u = kg*(v + 0.044715f*v*v*v);
                            v = 0.5f*v*(1.f + tanhf(u));
                            bf16 h = __float2bfloat16(v);
                            outh[o]=h; outl[o]=__float2bfloat16(v-__bfloat162float(h));
                        } else outf[o] = v;
                    }
                }
            }
        }
    }
}

// ---------------- tiled flash attention: 64 q x 64 k tiles ----------------
#define ASMEM (4*64*68*4)
__global__ void __launch_bounds__(256)
attn_kernel(const float* __restrict__ q, const float* __restrict__ k, const float* __restrict__ v,
            bf16* __restrict__ yh, bf16* __restrict__ yl){
    extern __shared__ float as_[];
    float *Qs=as_, *Ks=as_+64*68, *Vs=Ks+64*68, *Ps=Vs+64*68;
    int tid=threadIdx.x, ty=tid>>4, tx=tid&15;
    int qb=blockIdx.x, h=blockIdx.y, b=blockIdx.z;
    const float* qp = q + ((size_t)(b*TM_ + qb*64)*DM_ + h*DH_);
    const float* kp = k + ((size_t)b*TM_*DM_ + h*DH_);
    const float* vp = v + ((size_t)b*TM_*DM_ + h*DH_);
    #pragma unroll
    for (int i=0;i<4;i++){
        int id=tid+i*256; int r=id>>4, c=id&15;
        float4 f = *(const float4*)(qp + (size_t)r*DM_ + c*4);
        f.x*=0.125f; f.y*=0.125f; f.z*=0.125f; f.w*=0.125f;
        *(float4*)(Qs + r*68 + c*4) = f;
    }
    float O[4][4]={}, m[4], l[4]={};
    #pragma unroll
    for (int i=0;i<4;i++) m[i]=-1e30f;
    for (int kt=0; kt<=qb; kt++){
        __syncthreads();
        #pragma unroll
        for (int i=0;i<4;i++){
            int id=tid+i*256; int r=id>>4, c=id&15;
            *(float4*)(Ks + r*68 + c*4) = *(const float4*)(kp + (size_t)(kt*64+r)*DM_ + c*4);
            *(float4*)(Vs + r*68 + c*4) = *(const float4*)(vp + (size_t)(kt*64+r)*DM_ + c*4);
        }
        __syncthreads();
        float s[4][4]={};
        for (int d=0; d<64; d++){
            float qr[4], kr[4];
            #pragma unroll
            for (int i=0;i<4;i++) qr[i]=Qs[(4*ty+i)*68+d];
            #pragma unroll
            for (int j=0;j<4;j++) kr[j]=Ks[(4*tx+j)*68+d];
            #pragma unroll
            for (int i=0;i<4;i++)
                #pragma unroll
                for (int j=0;j<4;j++) s[i][j]+=qr[i]*kr[j];
        }
        if (kt==qb){
            #pragma unroll
            for (int i=0;i<4;i++)
                #pragma unroll
                for (int j=0;j<4;j++)
                    if (4*tx+j > 4*ty+i) s[i][j]=-1e30f;
        }
        #pragma unroll
        for (int i=0;i<4;i++){
            float rm = fmaxf(fmaxf(s[i][0],s[i][1]),fmaxf(s[i][2],s[i][3]));
            #pragma unroll
            for (int o=1;o<16;o<<=1) rm = fmaxf(rm, __shfl_xor_sync(~0u, rm, o));
            float nm = fmaxf(m[i], rm);
            float f = __expf(m[i]-nm);
            float p0=__expf(s[i][0]-nm), p1=__expf(s[i][1]-nm), p2=__expf(s[i][2]-nm), p3=__expf(s[i][3]-nm);
            float rs = p0+p1+p2+p3;
            #pragma unroll
            for (int o=1;o<16;o<<=1) rs += __shfl_xor_sync(~0u, rs, o);
            l[i] = l[i]*f + rs; m[i]=nm;
            #pragma unroll
            for (int j=0;j<4;j++) O[i][j]*=f;
            *(float4*)(Ps + (4*ty+i)*68 + 4*tx) = make_float4(p0,p1,p2,p3);
        }
        __syncthreads();
        for (int kk=0; kk<64; kk++){
            float4 vr = *(const float4*)(Vs + kk*68 + 4*tx);
            #pragma unroll
            for (int i=0;i<4;i++){
                float pr = Ps[(4*ty+i)*68+kk];
                O[i][0]+=pr*vr.x; O[i][1]+=pr*vr.y; O[i][2]+=pr*vr.z; O[i][3]+=pr*vr.w;
            }
        }
    }
    #pragma unroll
    for (int i=0;i<4;i++){
        float inv = 1.f/l[i];
        size_t o = (size_t)(b*TM_ + qb*64 + 4*ty+i)*DM_ + h*DH_ + 4*tx;
        #pragma unroll
        for (int j=0;j<4;j++){
            float val = O[i][j]*inv;
            bf16 hh = __float2bfloat16(val);
            yh[o+j]=hh; yl[o+j]=__float2bfloat16(val-__bfloat162float(hh));
        }
    }
}

// ---------------- launch ----------------
extern "C" void kernel_launch(void* const* d_in, const int* in_sizes, int n_in,
                              void* d_out, int out_size){
    const int*   idx  = (const int*)  d_in[0];
    const float* wte  = (const float*)d_in[1];
    const float* wpe  = (const float*)d_in[2];
    const float* ln1w = (const float*)d_in[3];
    const float* ln1b = (const float*)d_in[4];
    const float* Wq   = (const float*)d_in[5];
    const float* bq   = (const float*)d_in[6];
    const float* Wk   = (const float*)d_in[7];
    const float* bk   = (const float*)d_in[8];
    const float* Wv   = (const float*)d_in[9];
    const float* bv   = (const float*)d_in[10];
    const float* Wo   = (const float*)d_in[11];
    const float* bo   = (const float*)d_in[12];
    const float* ln2w = (const float*)d_in[13];
    const float* ln2b = (const float*)d_in[14];
    const float* Wfc  = (const float*)d_in[15];
    const float* bfc  = (const float*)d_in[16];
    const float* Wpr  = (const float*)d_in[17];
    const float* bpr  = (const float*)d_in[18];
    const float* lnfw = (const float*)d_in[19];
    const float* lnfb = (const float*)d_in[20];
    const float* Wlm  = (const float*)d_in[21];
    float* out = (float*)d_out;

    float *x,*qf,*kf,*vf;
    bf16 *hh,*hl,*yh,*yl,*fh,*fl;
    bf16 *wqh,*wql,*wkh,*wkl,*wvh,*wvl,*woh,*wol,*wfh,*wfl,*wph,*wpl,*wlh,*wll;
    cudaGetSymbolAddress((void**)&x, g_x);  cudaGetSymbolAddress((void**)&qf, g_qf);
    cudaGetSymbolAddress((void**)&kf, g_kf); cudaGetSymbolAddress((void**)&vf, g_vf);
    cudaGetSymbolAddress((void**)&hh, g_hh); cudaGetSymbolAddress((void**)&hl, g_hl);
    cudaGetSymbolAddress((void**)&yh, g_yh); cudaGetSymbolAddress((void**)&yl, g_yl);
    cudaGetSymbolAddress((void**)&fh, g_fh); cudaGetSymbolAddress((void**)&fl, g_fl);
    cudaGetSymbolAddress((void**)&wqh, g_Wqh); cudaGetSymbolAddress((void**)&wql, g_Wql);
    cudaGetSymbolAddress((void**)&wkh, g_Wkh); cudaGetSymbolAddress((void**)&wkl, g_Wkl);
    cudaGetSymbolAddress((void**)&wvh, g_Wvh); cudaGetSymbolAddress((void**)&wvl, g_Wvl);
    cudaGetSymbolAddress((void**)&woh, g_Woh); cudaGetSymbolAddress((void**)&wol, g_Wol);
    cudaGetSymbolAddress((void**)&wfh, g_Wfh); cudaGetSymbolAddress((void**)&wfl, g_Wfl);
    cudaGetSymbolAddress((void**)&wph, g_Wph); cudaGetSymbolAddress((void**)&wpl, g_Wpl);
    cudaGetSymbolAddress((void**)&wlh, g_Wlh); cudaGetSymbolAddress((void**)&wll, g_Wll);

    cudaFuncSetAttribute(tgemm<0>, cudaFuncAttributeMaxDynamicSharedMemorySize, TGSMEM);
    cudaFuncSetAttribute(tgemm<1>, cudaFuncAttributeMaxDynamicSharedMemorySize, TGSMEM);
    cudaFuncSetAttribute(tgemm<2>, cudaFuncAttributeMaxDynamicSharedMemorySize, TGSMEM);
    cudaFuncSetAttribute(tgemm<3>, cudaFuncAttributeMaxDynamicSharedMemorySize, TGSMEM);
    cudaFuncSetAttribute(attn_kernel, cudaFuncAttributeMaxDynamicSharedMemorySize, ASMEM);

    dim3 wb(32,8);
    wconv_kernel<<<dim3(DM_/32, DM_/32, LN_), wb>>>(Wq, wqh, wql, DM_, DM_);
    wconv_kernel<<<dim3(DM_/32, DM_/32, LN_), wb>>>(Wk, wkh, wkl, DM_, DM_);
    wconv_kernel<<<dim3(DM_/32, DM_/32, LN_), wb>>>(Wv, wvh, wvl, DM_, DM_);
    wconv_kernel<<<dim3(DM_/32, DM_/32, LN_), wb>>>(Wo, woh, wol, DM_, DM_);
    wconv_kernel<<<dim3(FF_/32, DM_/32, LN_), wb>>>(Wfc, wfh, wfl, DM_, FF_);
    wconv_kernel<<<dim3(DM_/32, FF_/32, LN_), wb>>>(Wpr, wph, wpl, FF_, DM_);
    wconv_kernel<<<dim3((VN_+31)/32, DM_/32, 1), wb>>>(Wlm, wlh, wll, DM_, VN_);

    embed_kernel<<<MR_, 192>>>(idx, wte, wpe, x);

    dim3 g768(6, 32), g3072(24, 32), glm((VN_+127)/128, 32);
    for (int l=0; l<LN_; l++){
        size_t wdd = (size_t)l*DM_*DM_, wff = (size_t)l*DM_*FF_;
        ln_kernel<<<MR_,192>>>(x, ln1w+l*DM_, ln1b+l*DM_, hh, hl);
        tgemm<0><<<g768,256,TGSMEM>>>(hh,hl, wqh+wdd,wql+wdd, bq+l*DM_, nullptr, qf,nullptr,nullptr, DM_, DM_);
        tgemm<0><<<g768,256,TGSMEM>>>(hh,hl, wkh+wdd,wkl+wdd, bk+l*DM_, nullptr, kf,nullptr,nullptr, DM_, DM_);
        tgemm<0><<<g768,256,TGSMEM>>>(hh,hl, wvh+wdd,wvl+wdd, bv+l*DM_, nullptr, vf,nullptr,nullptr, DM_, DM_);
        attn_kernel<<<dim3(16,HN_,BN_),256,ASMEM>>>(qf,kf,vf, yh,yl);
        tgemm<1><<<g768,256,TGSMEM>>>(yh,yl, woh+wdd,wol+wdd, bo+l*DM_, x, x,nullptr,nullptr, DM_, DM_);
        ln_kernel<<<MR_,192>>>(x, ln2w+l*DM_, ln2b+l*DM_, hh, hl);
        tgemm<2><<<g3072,256,TGSMEM>>>(hh,hl, wfh+wff,wfl+wff, bfc+(size_t)l*FF_, nullptr, nullptr, fh,fl, FF_, DM_);
        tgemm<1><<<g768,256,TGSMEM>>>(fh,fl, wph+wff,wpl+wff, bpr+l*DM_, x, x,nullptr,nullptr, DM_, FF_);
    }
    ln_kernel<<<MR_,192>>>(x, lnfw, lnfb, hh, hl);
    tgemm<3><<<glm,256,TGSMEM>>>(hh,hl, wlh,wll, nullptr, nullptr, out,nullptr,nullptr, VN_, DM_);
}

// round 6
// speedup vs baseline: 3.0485x; 1.3150x over previous
#include <cuda_runtime.h>
#include <cuda_bf16.h>
#include <math.h>
#include <stdint.h>

#define LN_ 12
#define HN_ 12
#define DM_ 768
#define TM_ 1024
#define BN_ 4
#define VN_ 50257
#define DH_ 64
#define MR_ (BN_*TM_)
#define FF_ (4*DM_)
#define QS_ (3*DM_)    // fused qkv row stride
#define DD_ (DM_*DM_)

typedef __nv_bfloat16 bf16;

// ---------------- scratch ----------------
__device__ float g_x  [MR_*DM_];
__device__ float g_qkv[MR_*QS_];
__device__ float g_bqkv[LN_*QS_];
__device__ bf16 g_hh[MR_*DM_], g_hl[MR_*DM_];
__device__ bf16 g_yh[MR_*DM_], g_yl[MR_*DM_];
__device__ bf16 g_fh[MR_*FF_], g_fl[MR_*FF_];
__device__ bf16 g_Wqkvh[LN_*3*DD_], g_Wqkvl[LN_*3*DD_];
__device__ bf16 g_Woh[LN_*DD_], g_Wol[LN_*DD_];
__device__ bf16 g_Wfh[LN_*DM_*FF_], g_Wfl[LN_*DM_*FF_];
__device__ bf16 g_Wph[LN_*DM_*FF_], g_Wpl[LN_*DM_*FF_];
__device__ bf16 g_Wlh[(size_t)VN_*DM_], g_Wll[(size_t)VN_*DM_];

// ---------------- PTX helpers (base sm_103 target only!) ----------------
__device__ __forceinline__ uint32_t su32(const void* p){
    uint32_t a; asm("{ .reg .u64 t; cvta.to.shared.u64 t, %1; cvt.u32.u64 %0, t; }":"=r"(a):"l"(p)); return a;
}
__device__ __forceinline__ void mma16816(float* c, const uint32_t* a, const uint32_t* b){
    asm volatile("mma.sync.aligned.m16n8k16.row.col.f32.bf16.bf16.f32 "
        "{%0,%1,%2,%3},{%4,%5,%6,%7},{%8,%9},{%0,%1,%2,%3};"
        : "+f"(c[0]),"+f"(c[1]),"+f"(c[2]),"+f"(c[3])
        : "r"(a[0]),"r"(a[1]),"r"(a[2]),"r"(a[3]),"r"(b[0]),"r"(b[1]));
}
__device__ __forceinline__ void ldsm4(uint32_t* r, uint32_t a){
    asm volatile("ldmatrix.sync.aligned.m8n8.x4.shared.b16 {%0,%1,%2,%3},[%4];"
        :"=r"(r[0]),"=r"(r[1]),"=r"(r[2]),"=r"(r[3]):"r"(a));
}
__device__ __forceinline__ void cpa(uint32_t d, const void* g, int vb){
    asm volatile("cp.async.cg.shared.global [%0],[%1],16,%2;"::"r"(d),"l"(g),"r"(vb):"memory");
}
__device__ __forceinline__ void cpcommit(){ asm volatile("cp.async.commit_group;":::"memory"); }
template<int N> __device__ __forceinline__ void cpwait(){ asm volatile("cp.async.wait_group %0;"::"n"(N):"memory"); }

// ---------------- weight transpose + split: W[K,N] -> [N,K] hi/lo ----------------
__global__ void wconv_kernel(const float* __restrict__ W, bf16* __restrict__ oh, bf16* __restrict__ ol,
                             int K, int N, size_t lstride){
    __shared__ float t[32][33];
    int l = blockIdx.z;
    W  += (size_t)l*K*N; oh += (size_t)l*lstride; ol += (size_t)l*lstride;
    int k0 = blockIdx.y*32, n0 = blockIdx.x*32;
    #pragma unroll
    for (int i=0;i<4;i++){
        int k = k0 + threadIdx.y + i*8, n = n0 + threadIdx.x;
        t[threadIdx.y+i*8][threadIdx.x] = (n<N) ? W[(size_t)k*N+n] : 0.f;
    }
    __syncthreads();
    #pragma unroll
    for (int i=0;i<4;i++){
        int n = n0 + threadIdx.y + i*8, k = k0 + threadIdx.x;
        if (n<N){
            float v = t[threadIdx.x][threadIdx.y+i*8];
            bf16 h = __float2bfloat16(v);
            oh[(size_t)n*K+k] = h;
            ol[(size_t)n*K+k] = __float2bfloat16(v - __bfloat162float(h));
        }
    }
}

// ---------------- bias concat ----------------
__global__ void bcat_kernel(const float* __restrict__ bq, const float* __restrict__ bk,
                            const float* __restrict__ bv, float* __restrict__ o){
    int l = blockIdx.x, t = threadIdx.x;
    o[l*QS_ + t]          = bq[l*DM_ + t];
    o[l*QS_ + DM_ + t]    = bk[l*DM_ + t];
    o[l*QS_ + 2*DM_ + t]  = bv[l*DM_ + t];
}

// ---------------- embedding ----------------
__global__ void embed_kernel(const int* __restrict__ idx, const float* __restrict__ wte,
                             const float* __restrict__ wpe, float* __restrict__ x){
    int row = blockIdx.x;
    float4 a = ((const float4*)(wte + (size_t)idx[row]*DM_))[threadIdx.x];
    float4 p = ((const float4*)(wpe + (size_t)(row&(TM_-1))*DM_))[threadIdx.x];
    a.x+=p.x; a.y+=p.y; a.z+=p.z; a.w+=p.w;
    ((float4*)(x + (size_t)row*DM_))[threadIdx.x] = a;
}

// ---------------- layernorm -> bf16 hi/lo (192 threads) ----------------
__global__ void ln_kernel(const float* __restrict__ x, const float* __restrict__ w, const float* __restrict__ b,
                          bf16* __restrict__ oh, bf16* __restrict__ ol){
    int row = blockIdx.x, tid = threadIdx.x;
    float4 v = ((const float4*)(x + (size_t)row*DM_))[tid];
    float s = v.x+v.y+v.z+v.w;
    float sq = v.x*v.x+v.y*v.y+v.z*v.z+v.w*v.w;
    __shared__ float ss[6], sp[6];
    #pragma unroll
    for (int o=16;o;o>>=1){ s+=__shfl_xor_sync(~0u,s,o); sq+=__shfl_xor_sync(~0u,sq,o); }
    if ((tid&31)==0){ ss[tid>>5]=s; sp[tid>>5]=sq; }
    __syncthreads();
    s=0; sq=0;
    #pragma unroll
    for (int i=0;i<6;i++){ s+=ss[i]; sq+=sp[i]; }
    float mean = s*(1.f/DM_), var = sq*(1.f/DM_)-mean*mean, rstd = rsqrtf(var+1e-5f);
    float4 wv = ((const float4*)w)[tid], bv = ((const float4*)b)[tid];
    float y[4] = {(v.x-mean)*rstd*wv.x+bv.x, (v.y-mean)*rstd*wv.y+bv.y,
                  (v.z-mean)*rstd*wv.z+bv.z, (v.w-mean)*rstd*wv.w+bv.w};
    bf16 hh[4], ll[4];
    #pragma unroll
    for (int i=0;i<4;i++){ hh[i]=__float2bfloat16(y[i]); ll[i]=__float2bfloat16(y[i]-__bfloat162float(hh[i])); }
    ((uint2*)(oh + (size_t)row*DM_))[tid] = *(uint2*)hh;
    ((uint2*)(ol + (size_t)row*DM_))[tid] = *(uint2*)ll;
}

// ---------------- HMMA GEMM: C[M,N] = (Ah+Al)[M,K] @ (Bh+Bl)[N,K]^T ----------------
// EPI: 0 bias->f32, 1 bias+res->f32, 2 bias+gelu->bf16 split, 3 none->f32
#define TILE_  10240
#define STG_   (4*TILE_)
#define TGSMEM (3*STG_)
template<int EPI>
__global__ void __launch_bounds__(256)
tgemm(const bf16* __restrict__ Ah, const bf16* __restrict__ Al,
      const bf16* __restrict__ Bh, const bf16* __restrict__ Bl,
      const float* __restrict__ bias, const float* __restrict__ res,
      float* __restrict__ outf, bf16* __restrict__ outh, bf16* __restrict__ outl,
      int N, int K){
    extern __shared__ char smem[];
    uint32_t sb = su32(smem);
    const int tid = threadIdx.x;
    const int m0 = blockIdx.y*128, n0 = blockIdx.x*128;
    const int NT = K >> 5;
    const bf16* srcs[4] = {Ah, Al, Bh, Bl};

    auto load_tile = [&](int kt){
        uint32_t base = sb + (uint32_t)(kt%3)*STG_;
        #pragma unroll
        for (int t=0;t<4;t++){
            const bf16* src = srcs[t];
            int row0 = (t<2)? m0 : n0;
            uint32_t tb = base + (uint32_t)t*TILE_;
            #pragma unroll
            for (int i=0;i<2;i++){
                int id = tid + i*256;
                int r = id>>2, c = id&3;
                const char* g = (const char*)(src + (size_t)(row0+r)*K + kt*32) + c*16;
                int vb = (t>=2 && (row0+r)>=N) ? 0 : 16;
                cpa(tb + (uint32_t)(r*80 + c*16), g, vb);
            }
        }
        cpcommit();
    };

    load_tile(0); load_tile(1); load_tile(2);

    const int l = tid & 31;
    const int wid = tid >> 5, wm = wid & 1, wn = wid >> 1;
    const uint32_t aoff = (uint32_t)((wm*64 + (l&7) + ((l>>3)&1)*8)*80 + (l>>4)*16);
    const uint32_t boff = (uint32_t)((wn*32 + (l&7) + (l>>4)*8)*80 + ((l>>3)&1)*16);

    float acc[4][4][4];
    #pragma unroll
    for (int i=0;i<4;i++) for (int j=0;j<4;j++) for (int r=0;r<4;r++) acc[i][j][r]=0.f;

    for (int kt=0; kt<NT; kt++){
        if (kt+3<=NT) cpwait<2>();
        else if (kt+2==NT) cpwait<1>();
        else cpwait<0>();
        __syncthreads();
        uint32_t base = sb + (uint32_t)(kt%3)*STG_;
        // load ALL fragments for both ks first (LDSM/MMA overlap)
        uint32_t ah[2][4][4], al_[2][4][4], bh[2][2][4], bl[2][2][4];
        #pragma unroll
        for (int ks=0; ks<2; ks++){
            #pragma unroll
            for (int mi=0; mi<4; mi++){
                ldsm4(ah[ks][mi],  base          + aoff + (uint32_t)(mi*16*80 + ks*32));
                ldsm4(al_[ks][mi], base + TILE_  + aoff + (uint32_t)(mi*16*80 + ks*32));
            }
            #pragma unroll
            for (int nb=0; nb<2; nb++){
                ldsm4(bh[ks][nb], base + 2*TILE_ + boff + (uint32_t)(nb*16*80 + ks*32));
                ldsm4(bl[ks][nb], base + 3*TILE_ + boff + (uint32_t)(nb*16*80 + ks*32));
            }
        }
        #pragma unroll
        for (int ks=0; ks<2; ks++){
            #pragma unroll
            for (int mi=0; mi<4; mi++){
                #pragma unroll
                for (int ni=0; ni<4; ni++){
                    const uint32_t* bhp = &bh[ks][ni>>1][(ni&1)*2];
                    const uint32_t* blp = &bl[ks][ni>>1][(ni&1)*2];
                    mma16816(acc[mi][ni], ah[ks][mi],  bhp);
                    mma16816(acc[mi][ni], al_[ks][mi], bhp);
                    mma16816(acc[mi][ni], ah[ks][mi],  blp);
                }
            }
        }
        __syncthreads();
        if (kt+3<NT) load_tile(kt+3);
    }

    const float kg = 0.7978845608028654f;
    #pragma unroll
    for (int mi=0; mi<4; mi++){
        #pragma unroll
        for (int ni=0; ni<4; ni++){
            #pragma unroll
            for (int half=0; half<2; half++){
                int r = m0 + wm*64 + mi*16 + (l>>2) + half*8;
                int c = n0 + wn*32 + ni*8 + (l&3)*2;
                float v0 = acc[mi][ni][half*2], v1 = acc[mi][ni][half*2+1];
                #pragma unroll
                for (int e=0; e<2; e++){
                    int cc = c + e;
                    if (cc < N){
                        float v = e ? v1 : v0;
                        size_t o = (size_t)r*N + cc;
                        if (EPI==0) outf[o] = v + bias[cc];
                        else if (EPI==1) outf[o] = v + bias[cc] + res[o];
                        else if (EPI==2){
                            v += bias[cc];
                            float u = kg*(v + 0.044715f*v*v*v);
                            v = 0.5f*v*(1.f + tanhf(u));
                            bf16 h = __float2bfloat16(v);
                            outh[o]=h; outl[o]=__float2bfloat16(v-__bfloat162float(h));
                        } else outf[o] = v;
                    }
                }
            }
        }
    }
}

// ---------------- flash attention: transposed Q/K smem (conflict-free) ----------------
#define ASMEM (4*64*68*4)
__global__ void __launch_bounds__(256)
attn_kernel(const float* __restrict__ qkv, bf16* __restrict__ yh, bf16* __restrict__ yl){
    extern __shared__ float as_[];
    float *Qt=as_, *Kt=as_+64*68, *Vs=Kt+64*68, *Ps=Vs+64*68;
    int tid=threadIdx.x, ty=tid>>4, tx=tid&15;
    int qb=blockIdx.x, h=blockIdx.y, b=blockIdx.z;
    const float* qp = qkv + (size_t)(b*TM_ + qb*64)*QS_ + h*DH_;
    const float* kp = qkv + (size_t)b*TM_*QS_ + DM_   + h*DH_;
    const float* vp = qkv + (size_t)b*TM_*QS_ + 2*DM_ + h*DH_;
    // Q transposed + scaled: Qt[d][m]
    #pragma unroll
    for (int i=0;i<4;i++){
        int id=tid+i*256; int r=id>>4, c=id&15;
        float4 f = *(const float4*)(qp + (size_t)r*QS_ + c*4);
        Qt[(4*c+0)*68 + r] = f.x*0.125f;
        Qt[(4*c+1)*68 + r] = f.y*0.125f;
        Qt[(4*c+2)*68 + r] = f.z*0.125f;
        Qt[(4*c+3)*68 + r] = f.w*0.125f;
    }
    float O[4][4]={}, m[4], l[4]={};
    #pragma unroll
    for (int i=0;i<4;i++) m[i]=-1e30f;
    for (int kt=0; kt<=qb; kt++){
        __syncthreads();
        #pragma unroll
        for (int i=0;i<4;i++){
            int id=tid+i*256; int r=id>>4, c=id&15;
            float4 kf = *(const float4*)(kp + (size_t)(kt*64+r)*QS_ + c*4);
            Kt[(4*c+0)*68 + r] = kf.x;
            Kt[(4*c+1)*68 + r] = kf.y;
            Kt[(4*c+2)*68 + r] = kf.z;
            Kt[(4*c+3)*68 + r] = kf.w;
            *(float4*)(Vs + r*68 + c*4) = *(const float4*)(vp + (size_t)(kt*64+r)*QS_ + c*4);
        }
        __syncthreads();
        float s[4][4]={};
        #pragma unroll 4
        for (int d=0; d<64; d++){
            float4 qv = *(const float4*)(Qt + d*68 + 4*ty);
            float4 kv = *(const float4*)(Kt + d*68 + 4*tx);
            float qr[4]={qv.x,qv.y,qv.z,qv.w}, kr[4]={kv.x,kv.y,kv.z,kv.w};
            #pragma unroll
            for (int i=0;i<4;i++)
                #pragma unroll
                for (int j=0;j<4;j++) s[i][j]+=qr[i]*kr[j];
        }
        if (kt==qb){
            #pragma unroll
            for (int i=0;i<4;i++)
                #pragma unroll
                for (int j=0;j<4;j++)
                    if (4*tx+j > 4*ty+i) s[i][j]=-1e30f;
        }
        #pragma unroll
        for (int i=0;i<4;i++){
            float rm = fmaxf(fmaxf(s[i][0],s[i][1]),fmaxf(s[i][2],s[i][3]));
            #pragma unroll
            for (int o=1;o<16;o<<=1) rm = fmaxf(rm, __shfl_xor_sync(~0u, rm, o));
            float nm = fmaxf(m[i], rm);
            float f = __expf(m[i]-nm);
            float p0=__expf(s[i][0]-nm), p1=__expf(s[i][1]-nm), p2=__expf(s[i][2]-nm), p3=__expf(s[i][3]-nm);
            float rs = p0+p1+p2+p3;
            #pragma unroll
            for (int o=1;o<16;o<<=1) rs += __shfl_xor_sync(~0u, rs, o);
            l[i] = l[i]*f + rs; m[i]=nm;
            #pragma unroll
            for (int j=0;j<4;j++) O[i][j]*=f;
            *(float4*)(Ps + (4*ty+i)*68 + 4*tx) = make_float4(p0,p1,p2,p3);
        }
        __syncthreads();
        #pragma unroll 4
        for (int kk=0; kk<64; kk++){
            float4 vr = *(const float4*)(Vs + kk*68 + 4*tx);
            #pragma unroll
            for (int i=0;i<4;i++){
                float pr = Ps[(4*ty+i)*68+kk];
                O[i][0]+=pr*vr.x; O[i][1]+=pr*vr.y; O[i][2]+=pr*vr.z; O[i][3]+=pr*vr.w;
            }
        }
    }
    #pragma unroll
    for (int i=0;i<4;i++){
        float inv = 1.f/l[i];
        size_t o = (size_t)(b*TM_ + qb*64 + 4*ty+i)*DM_ + h*DH_ + 4*tx;
        #pragma unroll
        for (int j=0;j<4;j++){
            float val = O[i][j]*inv;
            bf16 hh = __float2bfloat16(val);
            yh[o+j]=hh; yl[o+j]=__float2bfloat16(val-__bfloat162float(hh));
        }
    }
}

// ---------------- launch ----------------
extern "C" void kernel_launch(void* const* d_in, const int* in_sizes, int n_in,
                              void* d_out, int out_size){
    const int*   idx  = (const int*)  d_in[0];
    const float* wte  = (const float*)d_in[1];
    const float* wpe  = (const float*)d_in[2];
    const float* ln1w = (const float*)d_in[3];
    const float* ln1b = (const float*)d_in[4];
    const float* Wq   = (const float*)d_in[5];
    const float* bq   = (const float*)d_in[6];
    const float* Wk   = (const float*)d_in[7];
    const float* bk   = (const float*)d_in[8];
    const float* Wv   = (const float*)d_in[9];
    const float* bv   = (const float*)d_in[10];
    const float* Wo   = (const float*)d_in[11];
    const float* bo   = (const float*)d_in[12];
    const float* ln2w = (const float*)d_in[13];
    const float* ln2b = (const float*)d_in[14];
    const float* Wfc  = (const float*)d_in[15];
    const float* bfc  = (const float*)d_in[16];
    const float* Wpr  = (const float*)d_in[17];
    const float* bpr  = (const float*)d_in[18];
    const float* lnfw = (const float*)d_in[19];
    const float* lnfb = (const float*)d_in[20];
    const float* Wlm  = (const float*)d_in[21];
    float* out = (float*)d_out;

    float *x,*qkv,*bqkv;
    bf16 *hh,*hl,*yh,*yl,*fh,*fl;
    bf16 *wqkvh,*wqkvl,*woh,*wol,*wfh,*wfl,*wph,*wpl,*wlh,*wll;
    cudaGetSymbolAddress((void**)&x, g_x);
    cudaGetSymbolAddress((void**)&qkv, g_qkv);
    cudaGetSymbolAddress((void**)&bqkv, g_bqkv);
    cudaGetSymbolAddress((void**)&hh, g_hh); cudaGetSymbolAddress((void**)&hl, g_hl);
    cudaGetSymbolAddress((void**)&yh, g_yh); cudaGetSymbolAddress((void**)&yl, g_yl);
    cudaGetSymbolAddress((void**)&fh, g_fh); cudaGetSymbolAddress((void**)&fl, g_fl);
    cudaGetSymbolAddress((void**)&wqkvh, g_Wqkvh); cudaGetSymbolAddress((void**)&wqkvl, g_Wqkvl);
    cudaGetSymbolAddress((void**)&woh, g_Woh); cudaGetSymbolAddress((void**)&wol, g_Wol);
    cudaGetSymbolAddress((void**)&wfh, g_Wfh); cudaGetSymbolAddress((void**)&wfl, g_Wfl);
    cudaGetSymbolAddress((void**)&wph, g_Wph); cudaGetSymbolAddress((void**)&wpl, g_Wpl);
    cudaGetSymbolAddress((void**)&wlh, g_Wlh); cudaGetSymbolAddress((void**)&wll, g_Wll);

    cudaFuncSetAttribute(tgemm<0>, cudaFuncAttributeMaxDynamicSharedMemorySize, TGSMEM);
    cudaFuncSetAttribute(tgemm<1>, cudaFuncAttributeMaxDynamicSharedMemorySize, TGSMEM);
    cudaFuncSetAttribute(tgemm<2>, cudaFuncAttributeMaxDynamicSharedMemorySize, TGSMEM);
    cudaFuncSetAttribute(tgemm<3>, cudaFuncAttributeMaxDynamicSharedMemorySize, TGSMEM);
    cudaFuncSetAttribute(attn_kernel, cudaFuncAttributeMaxDynamicSharedMemorySize, ASMEM);

    dim3 wb(32,8);
    // QKV concatenated: rows [0,768)=Q, [768,1536)=K, [1536,2304)=V, per-layer stride 3*DD_
    wconv_kernel<<<dim3(DM_/32, DM_/32, LN_), wb>>>(Wq, wqkvh,          wqkvl,          DM_, DM_, (size_t)3*DD_);
    wconv_kernel<<<dim3(DM_/32, DM_/32, LN_), wb>>>(Wk, wqkvh + DD_,    wqkvl + DD_,    DM_, DM_, (size_t)3*DD_);
    wconv_kernel<<<dim3(DM_/32, DM_/32, LN_), wb>>>(Wv, wqkvh + 2*DD_,  wqkvl + 2*DD_,  DM_, DM_, (size_t)3*DD_);
    wconv_kernel<<<dim3(DM_/32, DM_/32, LN_), wb>>>(Wo, woh, wol, DM_, DM_, (size_t)DD_);
    wconv_kernel<<<dim3(FF_/32, DM_/32, LN_), wb>>>(Wfc, wfh, wfl, DM_, FF_, (size_t)DM_*FF_);
    wconv_kernel<<<dim3(DM_/32, FF_/32, LN_), wb>>>(Wpr, wph, wpl, FF_, DM_, (size_t)DM_*FF_);
    wconv_kernel<<<dim3((VN_+31)/32, DM_/32, 1), wb>>>(Wlm, wlh, wll, DM_, VN_, (size_t)VN_*DM_);
    bcat_kernel<<<LN_, DM_>>>(bq, bk, bv, bqkv);

    embed_kernel<<<MR_, 192>>>(idx, wte, wpe, x);

    dim3 gqkv(QS_/128, 32), g768(6, 32), g3072(24, 32), glm((VN_+127)/128, 32);
    for (int l=0; l<LN_; l++){
        size_t wdd = (size_t)l*DD_, wq3 = (size_t)l*3*DD_, wff = (size_t)l*DM_*FF_;
        ln_kernel<<<MR_,192>>>(x, ln1w+l*DM_, ln1b+l*DM_, hh, hl);
        tgemm<0><<<gqkv,256,TGSMEM>>>(hh,hl, wqkvh+wq3,wqkvl+wq3, bqkv+l*QS_, nullptr, qkv,nullptr,nullptr, QS_, DM_);
        attn_kernel<<<dim3(16,HN_,BN_),256,ASMEM>>>(qkv, yh,yl);
        tgemm<1><<<g768,256,TGSMEM>>>(yh,yl, woh+wdd,wol+wdd, bo+l*DM_, x, x,nullptr,nullptr, DM_, DM_);
        ln_kernel<<<MR_,192>>>(x, ln2w+l*DM_, ln2b+l*DM_, hh, hl);
        tgemm<2><<<g3072,256,TGSMEM>>>(hh,hl, wfh+wff,wfl+wff, bfc+(size_t)l*FF_, nullptr, nullptr, fh,fl, FF_, DM_);
        tgemm<1><<<g768,256,TGSMEM>>>(fh,fl, wph+wff,wpl+wff, bpr+l*DM_, x, x,nullptr,nullptr, DM_, FF_);
    }
    ln_kernel<<<MR_,192>>>(x, lnfw, lnfb, hh, hl);
    tgemm<3><<<glm,256,TGSMEM>>>(hh,hl, wlh,wll, nullptr, nullptr, out,nullptr,nullptr, VN_, DM_);
}

// round 7
// speedup vs baseline: 3.1640x; 1.0379x over previous
#include <cuda_runtime.h>
#include <cuda_bf16.h>
#include <math.h>
#include <stdint.h>

#define LN_ 12
#define HN_ 12
#define DM_ 768
#define TM_ 1024
#define BN_ 4
#define VN_ 50257
#define DH_ 64
#define MR_ (BN_*TM_)
#define FF_ (4*DM_)
#define QS_ (3*DM_)
#define DD_ (DM_*DM_)

typedef __nv_bfloat16 bf16;

// ---------------- scratch ----------------
__device__ float g_x  [MR_*DM_];
__device__ float g_qkv[MR_*QS_];
__device__ float g_bqkv[LN_*QS_];
__device__ bf16 g_hh[MR_*DM_], g_hl[MR_*DM_];
__device__ bf16 g_yh[MR_*DM_], g_yl[MR_*DM_];
__device__ bf16 g_fh[MR_*FF_], g_fl[MR_*FF_];
__device__ bf16 g_Wqkvh[LN_*3*DD_], g_Wqkvl[LN_*3*DD_];
__device__ bf16 g_Woh[LN_*DD_], g_Wol[LN_*DD_];
__device__ bf16 g_Wfh[LN_*DM_*FF_], g_Wfl[LN_*DM_*FF_];
__device__ bf16 g_Wph[LN_*DM_*FF_], g_Wpl[LN_*DM_*FF_];
__device__ bf16 g_Wlh[(size_t)VN_*DM_], g_Wll[(size_t)VN_*DM_];

// ---------------- PTX helpers (base sm_103 target only!) ----------------
__device__ __forceinline__ uint32_t su32(const void* p){
    uint32_t a; asm("{ .reg .u64 t; cvta.to.shared.u64 t, %1; cvt.u32.u64 %0, t; }":"=r"(a):"l"(p)); return a;
}
__device__ __forceinline__ void mma16816(float* c, const uint32_t* a, const uint32_t* b){
    asm volatile("mma.sync.aligned.m16n8k16.row.col.f32.bf16.bf16.f32 "
        "{%0,%1,%2,%3},{%4,%5,%6,%7},{%8,%9},{%0,%1,%2,%3};"
        : "+f"(c[0]),"+f"(c[1]),"+f"(c[2]),"+f"(c[3])
        : "r"(a[0]),"r"(a[1]),"r"(a[2]),"r"(a[3]),"r"(b[0]),"r"(b[1]));
}
__device__ __forceinline__ void ldsm4(uint32_t* r, uint32_t a){
    asm volatile("ldmatrix.sync.aligned.m8n8.x4.shared.b16 {%0,%1,%2,%3},[%4];"
        :"=r"(r[0]),"=r"(r[1]),"=r"(r[2]),"=r"(r[3]):"r"(a));
}
__device__ __forceinline__ void cpa(uint32_t d, const void* g, int vb){
    asm volatile("cp.async.cg.shared.global [%0],[%1],16,%2;"::"r"(d),"l"(g),"r"(vb):"memory");
}
__device__ __forceinline__ void cpcommit(){ asm volatile("cp.async.commit_group;":::"memory"); }
template<int N> __device__ __forceinline__ void cpwait(){ asm volatile("cp.async.wait_group %0;"::"n"(N):"memory"); }

// ---------------- weight transpose + split: W[K,N] -> [N,K] hi/lo ----------------
__global__ void wconv_kernel(const float* __restrict__ W, bf16* __restrict__ oh, bf16* __restrict__ ol,
                             int K, int N, size_t lstride){
    __shared__ float t[32][33];
    int l = blockIdx.z;
    W  += (size_t)l*K*N; oh += (size_t)l*lstride; ol += (size_t)l*lstride;
    int k0 = blockIdx.y*32, n0 = blockIdx.x*32;
    #pragma unroll
    for (int i=0;i<4;i++){
        int k = k0 + threadIdx.y + i*8, n = n0 + threadIdx.x;
        t[threadIdx.y+i*8][threadIdx.x] = (n<N) ? W[(size_t)k*N+n] : 0.f;
    }
    __syncthreads();
    #pragma unroll
    for (int i=0;i<4;i++){
        int n = n0 + threadIdx.y + i*8, k = k0 + threadIdx.x;
        if (n<N){
            float v = t[threadIdx.x][threadIdx.y+i*8];
            bf16 h = __float2bfloat16(v);
            oh[(size_t)n*K+k] = h;
            ol[(size_t)n*K+k] = __float2bfloat16(v - __bfloat162float(h));
        }
    }
}

// ---------------- bias concat ----------------
__global__ void bcat_kernel(const float* __restrict__ bq, const float* __restrict__ bk,
                            const float* __restrict__ bv, float* __restrict__ o){
    int l = blockIdx.x, t = threadIdx.x;
    o[l*QS_ + t]          = bq[l*DM_ + t];
    o[l*QS_ + DM_ + t]    = bk[l*DM_ + t];
    o[l*QS_ + 2*DM_ + t]  = bv[l*DM_ + t];
}

// ---------------- embedding ----------------
__global__ void embed_kernel(const int* __restrict__ idx, const float* __restrict__ wte,
                             const float* __restrict__ wpe, float* __restrict__ x){
    int row = blockIdx.x;
    float4 a = ((const float4*)(wte + (size_t)idx[row]*DM_))[threadIdx.x];
    float4 p = ((const float4*)(wpe + (size_t)(row&(TM_-1))*DM_))[threadIdx.x];
    a.x+=p.x; a.y+=p.y; a.z+=p.z; a.w+=p.w;
    ((float4*)(x + (size_t)row*DM_))[threadIdx.x] = a;
}

// ---------------- layernorm -> bf16 hi/lo (192 threads) ----------------
__global__ void ln_kernel(const float* __restrict__ x, const float* __restrict__ w, const float* __restrict__ b,
                          bf16* __restrict__ oh, bf16* __restrict__ ol){
    int row = blockIdx.x, tid = threadIdx.x;
    float4 v = ((const float4*)(x + (size_t)row*DM_))[tid];
    float s = v.x+v.y+v.z+v.w;
    float sq = v.x*v.x+v.y*v.y+v.z*v.z+v.w*v.w;
    __shared__ float ss[6], sp[6];
    #pragma unroll
    for (int o=16;o;o>>=1){ s+=__shfl_xor_sync(~0u,s,o); sq+=__shfl_xor_sync(~0u,sq,o); }
    if ((tid&31)==0){ ss[tid>>5]=s; sp[tid>>5]=sq; }
    __syncthreads();
    s=0; sq=0;
    #pragma unroll
    for (int i=0;i<6;i++){ s+=ss[i]; sq+=sp[i]; }
    float mean = s*(1.f/DM_), var = sq*(1.f/DM_)-mean*mean, rstd = rsqrtf(var+1e-5f);
    float4 wv = ((const float4*)w)[tid], bv = ((const float4*)b)[tid];
    float y[4] = {(v.x-mean)*rstd*wv.x+bv.x, (v.y-mean)*rstd*wv.y+bv.y,
                  (v.z-mean)*rstd*wv.z+bv.z, (v.w-mean)*rstd*wv.w+bv.w};
    bf16 hh[4], ll[4];
    #pragma unroll
    for (int i=0;i<4;i++){ hh[i]=__float2bfloat16(y[i]); ll[i]=__float2bfloat16(y[i]-__bfloat162float(hh[i])); }
    ((uint2*)(oh + (size_t)row*DM_))[tid] = *(uint2*)hh;
    ((uint2*)(ol + (size_t)row*DM_))[tid] = *(uint2*)ll;
}

// ---------------- HMMA GEMM: C[M,N] = (Ah+Al)[M,K] @ (Bh+Bl)[N,K]^T ----------------
// EPI: 0 bias->f32, 1 bias+res->f32, 2 bias+gelu->bf16 split, 3 none->f32
// BNT: CTA N-tile (128 -> 3-stage, warp 64x32; 256 -> 2-stage, warp 64x64)
// Grid: x = M blocks, y = N blocks (keeps activations L2-resident for lm_head)
#define TGSMEM 122880
template<int EPI, int BNT>
__global__ void __launch_bounds__(256)
tgemm(const bf16* __restrict__ Ah, const bf16* __restrict__ Al,
      const bf16* __restrict__ Bh, const bf16* __restrict__ Bl,
      const float* __restrict__ bias, const float* __restrict__ res,
      float* __restrict__ outf, bf16* __restrict__ outh, bf16* __restrict__ outl,
      int N, int K){
    constexpr int NSTG = (BNT==128) ? 3 : 2;
    constexpr int NI   = BNT/32;           // ni count per warp
    constexpr int WNW  = BNT/4;            // warp n-width
    constexpr uint32_t AT  = 128*80;       // Al offset
    constexpr uint32_t BT  = 2*128*80;     // Bh offset
    constexpr uint32_t BL  = BT + BNT*80;  // Bl offset
    constexpr uint32_t STGB = (uint32_t)(256 + 2*BNT)*80;

    extern __shared__ char smem[];
    uint32_t sb = su32(smem);
    const int tid = threadIdx.x;
    const int m0 = blockIdx.x*128, n0 = blockIdx.y*BNT;
    const int NT = K >> 5;

    auto load_tile = [&](int kt){
        uint32_t base = sb + (uint32_t)(kt%NSTG)*STGB;
        #pragma unroll
        for (int t=0;t<2;t++){
            const bf16* src = t ? Al : Ah;
            uint32_t tb = base + t*AT;
            #pragma unroll
            for (int i=0;i<2;i++){
                int id = tid + i*256; int r = id>>2, c = id&3;
                cpa(tb + (uint32_t)(r*80 + c*16),
                    (const char*)(src + (size_t)(m0+r)*K + kt*32) + c*16, 16);
            }
        }
        #pragma unroll
        for (int t=0;t<2;t++){
            const bf16* src = t ? Bl : Bh;
            uint32_t tb = base + BT + (uint32_t)t*(BNT*80);
            #pragma unroll
            for (int i=0;i<BNT/64;i++){
                int id = tid + i*256; int r = id>>2, c = id&3;
                int vb = (n0+r) < N ? 16 : 0;
                cpa(tb + (uint32_t)(r*80 + c*16),
                    (const char*)(src + (size_t)(n0+r)*K + kt*32) + c*16, vb);
            }
        }
        cpcommit();
    };

    #pragma unroll
    for (int s=0;s<NSTG;s++) if (s<NT) load_tile(s);

    const int l = tid & 31;
    const int wid = tid >> 5, wm = wid & 1, wn = wid >> 1;
    const uint32_t aoff = (uint32_t)((wm*64 + (l&7) + ((l>>3)&1)*8)*80 + (l>>4)*16);
    const uint32_t boff = (uint32_t)((wn*WNW + (l&7) + (l>>4)*8)*80 + ((l>>3)&1)*16);

    float acc[4][NI][4];
    #pragma unroll
    for (int i=0;i<4;i++) for (int j=0;j<NI;j++) for (int r=0;r<4;r++) acc[i][j][r]=0.f;

    for (int kt=0; kt<NT; kt++){
        if constexpr (NSTG==3){
            if (kt+3<=NT) cpwait<2>();
            else if (kt+2==NT) cpwait<1>();
            else cpwait<0>();
        } else {
            if (kt+2<=NT) cpwait<1>();
            else cpwait<0>();
        }
        __syncthreads();
        uint32_t base = sb + (uint32_t)(kt%NSTG)*STGB;
        if constexpr (BNT==128){
            uint32_t ah[2][4][4], al_[2][4][4], bh[2][2][4], bl[2][2][4];
            #pragma unroll
            for (int ks=0; ks<2; ks++){
                #pragma unroll
                for (int mi=0; mi<4; mi++){
                    ldsm4(ah[ks][mi],  base      + aoff + (uint32_t)(mi*16*80 + ks*32));
                    ldsm4(al_[ks][mi], base + AT + aoff + (uint32_t)(mi*16*80 + ks*32));
                }
                #pragma unroll
                for (int nb=0; nb<2; nb++){
                    ldsm4(bh[ks][nb], base + BT + boff + (uint32_t)(nb*16*80 + ks*32));
                    ldsm4(bl[ks][nb], base + BL + boff + (uint32_t)(nb*16*80 + ks*32));
                }
            }
            #pragma unroll
            for (int ks=0; ks<2; ks++)
                #pragma unroll
                for (int mi=0; mi<4; mi++)
                    #pragma unroll
                    for (int ni=0; ni<4; ni++){
                        const uint32_t* bhp = &bh[ks][ni>>1][(ni&1)*2];
                        const uint32_t* blp = &bl[ks][ni>>1][(ni&1)*2];
                        mma16816(acc[mi][ni], ah[ks][mi],  bhp);
                        mma16816(acc[mi][ni], al_[ks][mi], bhp);
                        mma16816(acc[mi][ni], ah[ks][mi],  blp);
                    }
        } else {
            #pragma unroll
            for (int ks=0; ks<2; ks++){
                uint32_t ah[4][4], al_[4][4], bh[4][4], bl[4][4];
                #pragma unroll
                for (int mi=0; mi<4; mi++){
                    ldsm4(ah[mi],  base      + aoff + (uint32_t)(mi*16*80 + ks*32));
                    ldsm4(al_[mi], base + AT + aoff + (uint32_t)(mi*16*80 + ks*32));
                }
                #pragma unroll
                for (int nb=0; nb<4; nb++){
                    ldsm4(bh[nb], base + BT + boff + (uint32_t)(nb*16*80 + ks*32));
                    ldsm4(bl[nb], base + BL + boff + (uint32_t)(nb*16*80 + ks*32));
                }
                #pragma unroll
                for (int mi=0; mi<4; mi++)
                    #pragma unroll
                    for (int ni=0; ni<8; ni++){
                        const uint32_t* bhp = &bh[ni>>1][(ni&1)*2];
                        const uint32_t* blp = &bl[ni>>1][(ni&1)*2];
                        mma16816(acc[mi][ni], ah[mi],  bhp);
                        mma16816(acc[mi][ni], al_[mi], bhp);
                        mma16816(acc[mi][ni], ah[mi],  blp);
                    }
            }
        }
        __syncthreads();
        if (kt+NSTG<NT) load_tile(kt+NSTG);
    }

    const float kg = 0.7978845608028654f;
    #pragma unroll
    for (int mi=0; mi<4; mi++){
        #pragma unroll
        for (int ni=0; ni<NI; ni++){
            #pragma unroll
            for (int half=0; half<2; half++){
                int r = m0 + wm*64 + mi*16 + (l>>2) + half*8;
                int c = n0 + wn*WNW + ni*8 + (l&3)*2;
                float v0 = acc[mi][ni][half*2], v1 = acc[mi][ni][half*2+1];
                #pragma unroll
                for (int e=0; e<2; e++){
                    int cc = c + e;
                    if (cc < N){
                        float v = e ? v1 : v0;
                        size_t o = (size_t)r*N + cc;
                        if (EPI==0) outf[o] = v + bias[cc];
                        else if (EPI==1) outf[o] = v + bias[cc] + res[o];
                        else if (EPI==2){
                            v += bias[cc];
                            float u = kg*(v + 0.044715f*v*v*v);
                            v = 0.5f*v*(1.f + tanhf(u));
                            bf16 h = __float2bfloat16(v);
                            outh[o]=h; outl[o]=__float2bfloat16(v-__bfloat162float(h));
                        } else outf[o] = v;
                    }
                }
            }
        }
    }
}

// ---------------- flash attention: transposed Q/K smem (conflict-free) ----------------
#define ASMEM (4*64*68*4)
__global__ void __launch_bounds__(256)
attn_kernel(const float* __restrict__ qkv, bf16* __restrict__ yh, bf16* __restrict__ yl){
    extern __shared__ float as_[];
    float *Qt=as_, *Kt=as_+64*68, *Vs=Kt+64*68, *Ps=Vs+64*68;
    int tid=threadIdx.x, ty=tid>>4, tx=tid&15;
    int qb=blockIdx.x, h=blockIdx.y, b=blockIdx.z;
    const float* qp = qkv + (size_t)(b*TM_ + qb*64)*QS_ + h*DH_;
    const float* kp = qkv + (size_t)b*TM_*QS_ + DM_   + h*DH_;
    const float* vp = qkv + (size_t)b*TM_*QS_ + 2*DM_ + h*DH_;
    #pragma unroll
    for (int i=0;i<4;i++){
        int id=tid+i*256; int r=id>>4, c=id&15;
        float4 f = *(const float4*)(qp + (size_t)r*QS_ + c*4);
        Qt[(4*c+0)*68 + r] = f.x*0.125f;
        Qt[(4*c+1)*68 + r] = f.y*0.125f;
        Qt[(4*c+2)*68 + r] = f.z*0.125f;
        Qt[(4*c+3)*68 + r] = f.w*0.125f;
    }
    float O[4][4]={}, m[4], l[4]={};
    #pragma unroll
    for (int i=0;i<4;i++) m[i]=-1e30f;
    for (int kt=0; kt<=qb; kt++){
        __syncthreads();
        #pragma unroll
        for (int i=0;i<4;i++){
            int id=tid+i*256; int r=id>>4, c=id&15;
            float4 kf = *(const float4*)(kp + (size_t)(kt*64+r)*QS_ + c*4);
            Kt[(4*c+0)*68 + r] = kf.x;
            Kt[(4*c+1)*68 + r] = kf.y;
            Kt[(4*c+2)*68 + r] = kf.z;
            Kt[(4*c+3)*68 + r] = kf.w;
            *(float4*)(Vs + r*68 + c*4) = *(const float4*)(vp + (size_t)(kt*64+r)*QS_ + c*4);
        }
        __syncthreads();
        float s[4][4]={};
        #pragma unroll 4
        for (int d=0; d<64; d++){
            float4 qv = *(const float4*)(Qt + d*68 + 4*ty);
            float4 kv = *(const float4*)(Kt + d*68 + 4*tx);
            float qr[4]={qv.x,qv.y,qv.z,qv.w}, kr[4]={kv.x,kv.y,kv.z,kv.w};
            #pragma unroll
            for (int i=0;i<4;i++)
                #pragma unroll
                for (int j=0;j<4;j++) s[i][j]+=qr[i]*kr[j];
        }
        if (kt==qb){
            #pragma unroll
            for (int i=0;i<4;i++)
                #pragma unroll
                for (int j=0;j<4;j++)
                    if (4*tx+j > 4*ty+i) s[i][j]=-1e30f;
        }
        #pragma unroll
        for (int i=0;i<4;i++){
            float rm = fmaxf(fmaxf(s[i][0],s[i][1]),fmaxf(s[i][2],s[i][3]));
            #pragma unroll
            for (int o=1;o<16;o<<=1) rm = fmaxf(rm, __shfl_xor_sync(~0u, rm, o));
            float nm = fmaxf(m[i], rm);
            float f = __expf(m[i]-nm);
            float p0=__expf(s[i][0]-nm), p1=__expf(s[i][1]-nm), p2=__expf(s[i][2]-nm), p3=__expf(s[i][3]-nm);
            float rs = p0+p1+p2+p3;
            #pragma unroll
            for (int o=1;o<16;o<<=1) rs += __shfl_xor_sync(~0u, rs, o);
            l[i] = l[i]*f + rs; m[i]=nm;
            #pragma unroll
            for (int j=0;j<4;j++) O[i][j]*=f;
            *(float4*)(Ps + (4*ty+i)*68 + 4*tx) = make_float4(p0,p1,p2,p3);
        }
        __syncthreads();
        #pragma unroll 4
        for (int kk=0; kk<64; kk++){
            float4 vr = *(const float4*)(Vs + kk*68 + 4*tx);
            #pragma unroll
            for (int i=0;i<4;i++){
                float pr = Ps[(4*ty+i)*68+kk];
                O[i][0]+=pr*vr.x; O[i][1]+=pr*vr.y; O[i][2]+=pr*vr.z; O[i][3]+=pr*vr.w;
            }
        }
    }
    #pragma unroll
    for (int i=0;i<4;i++){
        float inv = 1.f/l[i];
        size_t o = (size_t)(b*TM_ + qb*64 + 4*ty+i)*DM_ + h*DH_ + 4*tx;
        #pragma unroll
        for (int j=0;j<4;j++){
            float val = O[i][j]*inv;
            bf16 hh = __float2bfloat16(val);
            yh[o+j]=hh; yl[o+j]=__float2bfloat16(val-__bfloat162float(hh));
        }
    }
}

// ---------------- launch ----------------
extern "C" void kernel_launch(void* const* d_in, const int* in_sizes, int n_in,
                              void* d_out, int out_size){
    const int*   idx  = (const int*)  d_in[0];
    const float* wte  = (const float*)d_in[1];
    const float* wpe  = (const float*)d_in[2];
    const float* ln1w = (const float*)d_in[3];
    const float* ln1b = (const float*)d_in[4];
    const float* Wq   = (const float*)d_in[5];
    const float* bq   = (const float*)d_in[6];
    const float* Wk   = (const float*)d_in[7];
    const float* bk   = (const float*)d_in[8];
    const float* Wv   = (const float*)d_in[9];
    const float* bv   = (const float*)d_in[10];
    const float* Wo   = (const float*)d_in[11];
    const float* bo   = (const float*)d_in[12];
    const float* ln2w = (const float*)d_in[13];
    const float* ln2b = (const float*)d_in[14];
    const float* Wfc  = (const float*)d_in[15];
    const float* bfc  = (const float*)d_in[16];
    const float* Wpr  = (const float*)d_in[17];
    const float* bpr  = (const float*)d_in[18];
    const float* lnfw = (const float*)d_in[19];
    const float* lnfb = (const float*)d_in[20];
    const float* Wlm  = (const float*)d_in[21];
    float* out = (float*)d_out;

    float *x,*qkv,*bqkv;
    bf16 *hh,*hl,*yh,*yl,*fh,*fl;
    bf16 *wqkvh,*wqkvl,*woh,*wol,*wfh,*wfl,*wph,*wpl,*wlh,*wll;
    cudaGetSymbolAddress((void**)&x, g_x);
    cudaGetSymbolAddress((void**)&qkv, g_qkv);
    cudaGetSymbolAddress((void**)&bqkv, g_bqkv);
    cudaGetSymbolAddress((void**)&hh, g_hh); cudaGetSymbolAddress((void**)&hl, g_hl);
    cudaGetSymbolAddress((void**)&yh, g_yh); cudaGetSymbolAddress((void**)&yl, g_yl);
    cudaGetSymbolAddress((void**)&fh, g_fh); cudaGetSymbolAddress((void**)&fl, g_fl);
    cudaGetSymbolAddress((void**)&wqkvh, g_Wqkvh); cudaGetSymbolAddress((void**)&wqkvl, g_Wqkvl);
    cudaGetSymbolAddress((void**)&woh, g_Woh); cudaGetSymbolAddress((void**)&wol, g_Wol);
    cudaGetSymbolAddress((void**)&wfh, g_Wfh); cudaGetSymbolAddress((void**)&wfl, g_Wfl);
    cudaGetSymbolAddress((void**)&wph, g_Wph); cudaGetSymbolAddress((void**)&wpl, g_Wpl);
    cudaGetSymbolAddress((void**)&wlh, g_Wlh); cudaGetSymbolAddress((void**)&wll, g_Wll);

    cudaFuncSetAttribute(tgemm<0,256>, cudaFuncAttributeMaxDynamicSharedMemorySize, TGSMEM);
    cudaFuncSetAttribute(tgemm<1,128>, cudaFuncAttributeMaxDynamicSharedMemorySize, TGSMEM);
    cudaFuncSetAttribute(tgemm<2,256>, cudaFuncAttributeMaxDynamicSharedMemorySize, TGSMEM);
    cudaFuncSetAttribute(tgemm<3,256>, cudaFuncAttributeMaxDynamicSharedMemorySize, TGSMEM);
    cudaFuncSetAttribute(attn_kernel, cudaFuncAttributeMaxDynamicSharedMemorySize, ASMEM);

    dim3 wb(32,8);
    wconv_kernel<<<dim3(DM_/32, DM_/32, LN_), wb>>>(Wq, wqkvh,          wqkvl,          DM_, DM_, (size_t)3*DD_);
    wconv_kernel<<<dim3(DM_/32, DM_/32, LN_), wb>>>(Wk, wqkvh + DD_,    wqkvl + DD_,    DM_, DM_, (size_t)3*DD_);
    wconv_kernel<<<dim3(DM_/32, DM_/32, LN_), wb>>>(Wv, wqkvh + 2*DD_,  wqkvl + 2*DD_,  DM_, DM_, (size_t)3*DD_);
    wconv_kernel<<<dim3(DM_/32, DM_/32, LN_), wb>>>(Wo, woh, wol, DM_, DM_, (size_t)DD_);
    wconv_kernel<<<dim3(FF_/32, DM_/32, LN_), wb>>>(Wfc, wfh, wfl, DM_, FF_, (size_t)DM_*FF_);
    wconv_kernel<<<dim3(DM_/32, FF_/32, LN_), wb>>>(Wpr, wph, wpl, FF_, DM_, (size_t)DM_*FF_);
    wconv_kernel<<<dim3((VN_+31)/32, DM_/32, 1), wb>>>(Wlm, wlh, wll, DM_, VN_, (size_t)VN_*DM_);
    bcat_kernel<<<LN_, DM_>>>(bq, bk, bv, bqkv);

    embed_kernel<<<MR_, 192>>>(idx, wte, wpe, x);

    dim3 gqkv(32, QS_/256), g768(32, 6), g3072(32, FF_/256), glm(32, (VN_+255)/256);
    for (int l=0; l<LN_; l++){
        size_t wdd = (size_t)l*DD_, wq3 = (size_t)l*3*DD_, wff = (size_t)l*DM_*FF_;
        ln_kernel<<<MR_,192>>>(x, ln1w+l*DM_, ln1b+l*DM_, hh, hl);
        tgemm<0,256><<<gqkv,256,TGSMEM>>>(hh,hl, wqkvh+wq3,wqkvl+wq3, bqkv+l*QS_, nullptr, qkv,nullptr,nullptr, QS_, DM_);
        attn_kernel<<<dim3(16,HN_,BN_),256,ASMEM>>>(qkv, yh,yl);
        tgemm<1,128><<<g768,256,TGSMEM>>>(yh,yl, woh+wdd,wol+wdd, bo+l*DM_, x, x,nullptr,nullptr, DM_, DM_);
        ln_kernel<<<MR_,192>>>(x, ln2w+l*DM_, ln2b+l*DM_, hh, hl);
        tgemm<2,256><<<g3072,256,TGSMEM>>>(hh,hl, wfh+wff,wfl+wff, bfc+(size_t)l*FF_, nullptr, nullptr, fh,fl, FF_, DM_);
        tgemm<1,128><<<g768,256,TGSMEM>>>(fh,fl, wph+wff,wpl+wff, bpr+l*DM_, x, x,nullptr,nullptr, DM_, FF_);
    }
    ln_kernel<<<MR_,192>>>(x, lnfw, lnfb, hh, hl);
    tgemm<3,256><<<glm,256,TGSMEM>>>(hh,hl, wlh,wll, nullptr, nullptr, out,nullptr,nullptr, VN_, DM_);
}

// round 8
// speedup vs baseline: 3.7194x; 1.1755x over previous
#include <cuda_runtime.h>
#include <cuda_fp16.h>
#include <math.h>
#include <stdint.h>

#define LN_ 12
#define HN_ 12
#define DM_ 768
#define TM_ 1024
#define BN_ 4
#define VN_ 50257
#define DH_ 64
#define MR_ (BN_*TM_)
#define FF_ (4*DM_)
#define QS_ (3*DM_)
#define DD_ (DM_*DM_)

// ---------------- scratch ----------------
__device__ float g_x  [MR_*DM_];
__device__ float g_qkv[MR_*QS_];
__device__ float g_bqkv[LN_*QS_];
__device__ __half g_h[MR_*DM_];
__device__ __half g_y[MR_*DM_];
__device__ __half g_f[MR_*FF_];
__device__ __half g_Wqkv[LN_*3*DD_];
__device__ __half g_Wo[LN_*DD_];
__device__ __half g_Wf[LN_*DM_*FF_];
__device__ __half g_Wp[LN_*DM_*FF_];
__device__ __half g_Wlm[(size_t)VN_*DM_];

// ---------------- PTX helpers (base sm_103 target only!) ----------------
__device__ __forceinline__ uint32_t su32(const void* p){
    uint32_t a; asm("{ .reg .u64 t; cvta.to.shared.u64 t, %1; cvt.u32.u64 %0, t; }":"=r"(a):"l"(p)); return a;
}
__device__ __forceinline__ void mma16816(float* c, const uint32_t* a, const uint32_t* b){
    asm volatile("mma.sync.aligned.m16n8k16.row.col.f32.f16.f16.f32 "
        "{%0,%1,%2,%3},{%4,%5,%6,%7},{%8,%9},{%0,%1,%2,%3};"
        : "+f"(c[0]),"+f"(c[1]),"+f"(c[2]),"+f"(c[3])
        : "r"(a[0]),"r"(a[1]),"r"(a[2]),"r"(a[3]),"r"(b[0]),"r"(b[1]));
}
__device__ __forceinline__ void ldsm4(uint32_t* r, uint32_t a){
    asm volatile("ldmatrix.sync.aligned.m8n8.x4.shared.b16 {%0,%1,%2,%3},[%4];"
        :"=r"(r[0]),"=r"(r[1]),"=r"(r[2]),"=r"(r[3]):"r"(a));
}
__device__ __forceinline__ void cpa(uint32_t d, const void* g, int vb){
    asm volatile("cp.async.cg.shared.global [%0],[%1],16,%2;"::"r"(d),"l"(g),"r"(vb):"memory");
}
__device__ __forceinline__ void cpcommit(){ asm volatile("cp.async.commit_group;":::"memory"); }
template<int N> __device__ __forceinline__ void cpwait(){ asm volatile("cp.async.wait_group %0;"::"n"(N):"memory"); }

// ---------------- weight transpose + fp16 convert: W[K,N] -> [N,K] ----------------
__global__ void wconv_kernel(const float* __restrict__ W, __half* __restrict__ o,
                             int K, int N, size_t lstride){
    __shared__ float t[32][33];
    int l = blockIdx.z;
    W += (size_t)l*K*N; o += (size_t)l*lstride;
    int k0 = blockIdx.y*32, n0 = blockIdx.x*32;
    #pragma unroll
    for (int i=0;i<4;i++){
        int k = k0 + threadIdx.y + i*8, n = n0 + threadIdx.x;
        t[threadIdx.y+i*8][threadIdx.x] = (n<N) ? W[(size_t)k*N+n] : 0.f;
    }
    __syncthreads();
    #pragma unroll
    for (int i=0;i<4;i++){
        int n = n0 + threadIdx.y + i*8, k = k0 + threadIdx.x;
        if (n<N) o[(size_t)n*K+k] = __float2half(t[threadIdx.x][threadIdx.y+i*8]);
    }
}

// ---------------- bias concat ----------------
__global__ void bcat_kernel(const float* __restrict__ bq, const float* __restrict__ bk,
                            const float* __restrict__ bv, float* __restrict__ o){
    int l = blockIdx.x, t = threadIdx.x;
    o[l*QS_ + t]          = bq[l*DM_ + t];
    o[l*QS_ + DM_ + t]    = bk[l*DM_ + t];
    o[l*QS_ + 2*DM_ + t]  = bv[l*DM_ + t];
}

// ---------------- embedding ----------------
__global__ void embed_kernel(const int* __restrict__ idx, const float* __restrict__ wte,
                             const float* __restrict__ wpe, float* __restrict__ x){
    int row = blockIdx.x;
    float4 a = ((const float4*)(wte + (size_t)idx[row]*DM_))[threadIdx.x];
    float4 p = ((const float4*)(wpe + (size_t)(row&(TM_-1))*DM_))[threadIdx.x];
    a.x+=p.x; a.y+=p.y; a.z+=p.z; a.w+=p.w;
    ((float4*)(x + (size_t)row*DM_))[threadIdx.x] = a;
}

// ---------------- layernorm -> fp16 (192 threads) ----------------
__global__ void ln_kernel(const float* __restrict__ x, const float* __restrict__ w, const float* __restrict__ b,
                          __half* __restrict__ oh){
    int row = blockIdx.x, tid = threadIdx.x;
    float4 v = ((const float4*)(x + (size_t)row*DM_))[tid];
    float s = v.x+v.y+v.z+v.w;
    float sq = v.x*v.x+v.y*v.y+v.z*v.z+v.w*v.w;
    __shared__ float ss[6], sp[6];
    #pragma unroll
    for (int o=16;o;o>>=1){ s+=__shfl_xor_sync(~0u,s,o); sq+=__shfl_xor_sync(~0u,sq,o); }
    if ((tid&31)==0){ ss[tid>>5]=s; sp[tid>>5]=sq; }
    __syncthreads();
    s=0; sq=0;
    #pragma unroll
    for (int i=0;i<6;i++){ s+=ss[i]; sq+=sp[i]; }
    float mean = s*(1.f/DM_), var = sq*(1.f/DM_)-mean*mean, rstd = rsqrtf(var+1e-5f);
    float4 wv = ((const float4*)w)[tid], bv = ((const float4*)b)[tid];
    __half hh[4];
    hh[0] = __float2half((v.x-mean)*rstd*wv.x+bv.x);
    hh[1] = __float2half((v.y-mean)*rstd*wv.y+bv.y);
    hh[2] = __float2half((v.z-mean)*rstd*wv.z+bv.z);
    hh[3] = __float2half((v.w-mean)*rstd*wv.w+bv.w);
    ((uint2*)(oh + (size_t)row*DM_))[tid] = *(uint2*)hh;
}

// ---------------- HMMA GEMM (fp16 single-pass): C[M,N] = A[M,K] @ B[N,K]^T ----------------
// EPI: 0 bias->f32, 1 bias+res->f32, 2 bias+gelu->fp16, 3 none->f32
// CTA 128x128x32, 3-stage cp.async, 8 warps (2m x 4n), 2 CTAs/SM.
#define STGB   20480u          // (128 A rows + 128 B rows) * 80B
#define BT_    10240u          // B offset within stage
#define TGSMEM (3*20480)
template<int EPI>
__global__ void __launch_bounds__(256,2)
tgemm(const __half* __restrict__ A, const __half* __restrict__ B,
      const float* __restrict__ bias, const float* __restrict__ res,
      float* __restrict__ outf, __half* __restrict__ outh,
      int N, int K){
    extern __shared__ char smem[];
    uint32_t sb = su32(smem);
    const int tid = threadIdx.x;
    const int m0 = blockIdx.x*128, n0 = blockIdx.y*128;
    const int NT = K >> 5;

    auto load_tile = [&](int kt){
        uint32_t base = sb + (uint32_t)(kt%3)*STGB;
        #pragma unroll
        for (int i=0;i<2;i++){
            int id = tid + i*256; int r = id>>2, c = id&3;
            cpa(base + (uint32_t)(r*80 + c*16),
                (const char*)(A + (size_t)(m0+r)*K + kt*32) + c*16, 16);
        }
        #pragma unroll
        for (int i=0;i<2;i++){
            int id = tid + i*256; int r = id>>2, c = id&3;
            int vb = (n0+r) < N ? 16 : 0;
            cpa(base + BT_ + (uint32_t)(r*80 + c*16),
                (const char*)(B + (size_t)(n0+r)*K + kt*32) + c*16, vb);
        }
        cpcommit();
    };

    load_tile(0); if (NT>1) load_tile(1); if (NT>2) load_tile(2);

    const int l = tid & 31;
    const int wid = tid >> 5, wm = wid & 1, wn = wid >> 1;
    const uint32_t aoff = (uint32_t)((wm*64 + (l&7) + ((l>>3)&1)*8)*80 + (l>>4)*16);
    const uint32_t boff = (uint32_t)((wn*32 + (l&7) + (l>>4)*8)*80 + ((l>>3)&1)*16);

    float acc[4][4][4];
    #pragma unroll
    for (int i=0;i<4;i++) for (int j=0;j<4;j++) for (int r=0;r<4;r++) acc[i][j][r]=0.f;

    for (int kt=0; kt<NT; kt++){
        if (kt+3<=NT) cpwait<2>();
        else if (kt+2==NT) cpwait<1>();
        else cpwait<0>();
        __syncthreads();
        uint32_t base = sb + (uint32_t)(kt%3)*STGB;
        #pragma unroll
        for (int ks=0; ks<2; ks++){
            uint32_t af[4][4], bf_[2][4];
            #pragma unroll
            for (int mi=0; mi<4; mi++)
                ldsm4(af[mi], base + aoff + (uint32_t)(mi*16*80 + ks*32));
            #pragma unroll
            for (int nb=0; nb<2; nb++)
                ldsm4(bf_[nb], base + BT_ + boff + (uint32_t)(nb*16*80 + ks*32));
            #pragma unroll
            for (int mi=0; mi<4; mi++)
                #pragma unroll
                for (int ni=0; ni<4; ni++)
                    mma16816(acc[mi][ni], af[mi], &bf_[ni>>1][(ni&1)*2]);
        }
        __syncthreads();
        if (kt+3<NT) load_tile(kt+3);
    }

    const float kg = 0.7978845608028654f;
    #pragma unroll
    for (int mi=0; mi<4; mi++){
        #pragma unroll
        for (int ni=0; ni<4; ni++){
            #pragma unroll
            for (int half_=0; half_<2; half_++){
                int r = m0 + wm*64 + mi*16 + (l>>2) + half_*8;
                int c = n0 + wn*32 + ni*8 + (l&3)*2;
                float v0 = acc[mi][ni][half_*2], v1 = acc[mi][ni][half_*2+1];
                #pragma unroll
                for (int e=0; e<2; e++){
                    int cc = c + e;
                    if (cc < N){
                        float v = e ? v1 : v0;
                        size_t o = (size_t)r*N + cc;
                        if (EPI==0) outf[o] = v + bias[cc];
                        else if (EPI==1) outf[o] = v + bias[cc] + res[o];
                        else if (EPI==2){
                            v += bias[cc];
                            float u = kg*(v + 0.044715f*v*v*v);
                            v = 0.5f*v*(1.f + tanhf(u));
                            outh[o] = __float2half(v);
                        } else outf[o] = v;
                    }
                }
            }
        }
    }
}

// ---------------- flash attention: transposed Q/K smem (conflict-free) ----------------
#define ASMEM (4*64*68*4)
__global__ void __launch_bounds__(256)
attn_kernel(const float* __restrict__ qkv, __half* __restrict__ y){
    extern __shared__ float as_[];
    float *Qt=as_, *Kt=as_+64*68, *Vs=Kt+64*68, *Ps=Vs+64*68;
    int tid=threadIdx.x, ty=tid>>4, tx=tid&15;
    int qb=blockIdx.x, h=blockIdx.y, b=blockIdx.z;
    const float* qp = qkv + (size_t)(b*TM_ + qb*64)*QS_ + h*DH_;
    const float* kp = qkv + (size_t)b*TM_*QS_ + DM_   + h*DH_;
    const float* vp = qkv + (size_t)b*TM_*QS_ + 2*DM_ + h*DH_;
    #pragma unroll
    for (int i=0;i<4;i++){
        int id=tid+i*256; int r=id>>4, c=id&15;
        float4 f = *(const float4*)(qp + (size_t)r*QS_ + c*4);
        Qt[(4*c+0)*68 + r] = f.x*0.125f;
        Qt[(4*c+1)*68 + r] = f.y*0.125f;
        Qt[(4*c+2)*68 + r] = f.z*0.125f;
        Qt[(4*c+3)*68 + r] = f.w*0.125f;
    }
    float O[4][4]={}, m[4], l[4]={};
    #pragma unroll
    for (int i=0;i<4;i++) m[i]=-1e30f;
    for (int kt=0; kt<=qb; kt++){
        __syncthreads();
        #pragma unroll
        for (int i=0;i<4;i++){
            int id=tid+i*256; int r=id>>4, c=id&15;
            float4 kf = *(const float4*)(kp + (size_t)(kt*64+r)*QS_ + c*4);
            Kt[(4*c+0)*68 + r] = kf.x;
            Kt[(4*c+1)*68 + r] = kf.y;
            Kt[(4*c+2)*68 + r] = kf.z;
            Kt[(4*c+3)*68 + r] = kf.w;
            *(float4*)(Vs + r*68 + c*4) = *(const float4*)(vp + (size_t)(kt*64+r)*QS_ + c*4);
        }
        __syncthreads();
        float s[4][4]={};
        #pragma unroll 4
        for (int d=0; d<64; d++){
            float4 qv = *(const float4*)(Qt + d*68 + 4*ty);
            float4 kv = *(const float4*)(Kt + d*68 + 4*tx);
            float qr[4]={qv.x,qv.y,qv.z,qv.w}, kr[4]={kv.x,kv.y,kv.z,kv.w};
            #pragma unroll
            for (int i=0;i<4;i++)
                #pragma unroll
                for (int j=0;j<4;j++) s[i][j]+=qr[i]*kr[j];
        }
        if (kt==qb){
            #pragma unroll
            for (int i=0;i<4;i++)
                #pragma unroll
                for (int j=0;j<4;j++)
                    if (4*tx+j > 4*ty+i) s[i][j]=-1e30f;
        }
        #pragma unroll
        for (int i=0;i<4;i++){
            float rm = fmaxf(fmaxf(s[i][0],s[i][1]),fmaxf(s[i][2],s[i][3]));
            #pragma unroll
            for (int o=1;o<16;o<<=1) rm = fmaxf(rm, __shfl_xor_sync(~0u, rm, o));
            float nm = fmaxf(m[i], rm);
            float f = __expf(m[i]-nm);
            float p0=__expf(s[i][0]-nm), p1=__expf(s[i][1]-nm), p2=__expf(s[i][2]-nm), p3=__expf(s[i][3]-nm);
            float rs = p0+p1+p2+p3;
            #pragma unroll
            for (int o=1;o<16;o<<=1) rs += __shfl_xor_sync(~0u, rs, o);
            l[i] = l[i]*f + rs; m[i]=nm;
            #pragma unroll
            for (int j=0;j<4;j++) O[i][j]*=f;
            *(float4*)(Ps + (4*ty+i)*68 + 4*tx) = make_float4(p0,p1,p2,p3);
        }
        __syncthreads();
        #pragma unroll 4
        for (int kk=0; kk<64; kk++){
            float4 vr = *(const float4*)(Vs + kk*68 + 4*tx);
            #pragma unroll
            for (int i=0;i<4;i++){
                float pr = Ps[(4*ty+i)*68+kk];
                O[i][0]+=pr*vr.x; O[i][1]+=pr*vr.y; O[i][2]+=pr*vr.z; O[i][3]+=pr*vr.w;
            }
        }
    }
    #pragma unroll
    for (int i=0;i<4;i++){
        float inv = 1.f/l[i];
        size_t o = (size_t)(b*TM_ + qb*64 + 4*ty+i)*DM_ + h*DH_ + 4*tx;
        __half hv[4];
        #pragma unroll
        for (int j=0;j<4;j++) hv[j] = __float2half(O[i][j]*inv);
        *(uint2*)(y + o) = *(uint2*)hv;
    }
}

// ---------------- launch ----------------
extern "C" void kernel_launch(void* const* d_in, const int* in_sizes, int n_in,
                              void* d_out, int out_size){
    const int*   idx  = (const int*)  d_in[0];
    const float* wte  = (const float*)d_in[1];
    const float* wpe  = (const float*)d_in[2];
    const float* ln1w = (const float*)d_in[3];
    const float* ln1b = (const float*)d_in[4];
    const float* Wq   = (const float*)d_in[5];
    const float* bq   = (const float*)d_in[6];
    const float* Wk   = (const float*)d_in[7];
    const float* bk   = (const float*)d_in[8];
    const float* Wv   = (const float*)d_in[9];
    const float* bv   = (const float*)d_in[10];
    const float* Wo   = (const float*)d_in[11];
    const float* bo   = (const float*)d_in[12];
    const float* ln2w = (const float*)d_in[13];
    const float* ln2b = (const float*)d_in[14];
    const float* Wfc  = (const float*)d_in[15];
    const float* bfc  = (const float*)d_in[16];
    const float* Wpr  = (const float*)d_in[17];
    const float* bpr  = (const float*)d_in[18];
    const float* lnfw = (const float*)d_in[19];
    const float* lnfb = (const float*)d_in[20];
    const float* Wlm  = (const float*)d_in[21];
    float* out = (float*)d_out;

    float *x,*qkv,*bqkv;
    __half *h,*y,*f,*wqkv,*wo,*wf,*wp,*wlm;
    cudaGetSymbolAddress((void**)&x, g_x);
    cudaGetSymbolAddress((void**)&qkv, g_qkv);
    cudaGetSymbolAddress((void**)&bqkv, g_bqkv);
    cudaGetSymbolAddress((void**)&h, g_h);
    cudaGetSymbolAddress((void**)&y, g_y);
    cudaGetSymbolAddress((void**)&f, g_f);
    cudaGetSymbolAddress((void**)&wqkv, g_Wqkv);
    cudaGetSymbolAddress((void**)&wo, g_Wo);
    cudaGetSymbolAddress((void**)&wf, g_Wf);
    cudaGetSymbolAddress((void**)&wp, g_Wp);
    cudaGetSymbolAddress((void**)&wlm, g_Wlm);

    cudaFuncSetAttribute(tgemm<0>, cudaFuncAttributeMaxDynamicSharedMemorySize, TGSMEM);
    cudaFuncSetAttribute(tgemm<1>, cudaFuncAttributeMaxDynamicSharedMemorySize, TGSMEM);
    cudaFuncSetAttribute(tgemm<2>, cudaFuncAttributeMaxDynamicSharedMemorySize, TGSMEM);
    cudaFuncSetAttribute(tgemm<3>, cudaFuncAttributeMaxDynamicSharedMemorySize, TGSMEM);
    cudaFuncSetAttribute(attn_kernel, cudaFuncAttributeMaxDynamicSharedMemorySize, ASMEM);

    dim3 wb(32,8);
    wconv_kernel<<<dim3(DM_/32, DM_/32, LN_), wb>>>(Wq, wqkv,          DM_, DM_, (size_t)3*DD_);
    wconv_kernel<<<dim3(DM_/32, DM_/32, LN_), wb>>>(Wk, wqkv + DD_,    DM_, DM_, (size_t)3*DD_);
    wconv_kernel<<<dim3(DM_/32, DM_/32, LN_), wb>>>(Wv, wqkv + 2*DD_,  DM_, DM_, (size_t)3*DD_);
    wconv_kernel<<<dim3(DM_/32, DM_/32, LN_), wb>>>(Wo, wo, DM_, DM_, (size_t)DD_);
    wconv_kernel<<<dim3(FF_/32, DM_/32, LN_), wb>>>(Wfc, wf, DM_, FF_, (size_t)DM_*FF_);
    wconv_kernel<<<dim3(DM_/32, FF_/32, LN_), wb>>>(Wpr, wp, FF_, DM_, (size_t)DM_*FF_);
    wconv_kernel<<<dim3((VN_+31)/32, DM_/32, 1), wb>>>(Wlm, wlm, DM_, VN_, (size_t)VN_*DM_);
    bcat_kernel<<<LN_, DM_>>>(bq, bk, bv, bqkv);

    embed_kernel<<<MR_, 192>>>(idx, wte, wpe, x);

    dim3 gqkv(32, QS_/128), g768(32, 6), g3072(32, FF_/128), glm(32, (VN_+127)/128);
    for (int l=0; l<LN_; l++){
        size_t wdd = (size_t)l*DD_, wq3 = (size_t)l*3*DD_, wff = (size_t)l*DM_*FF_;
        ln_kernel<<<MR_,192>>>(x, ln1w+l*DM_, ln1b+l*DM_, h);
        tgemm<0><<<gqkv,256,TGSMEM>>>(h, wqkv+wq3, bqkv+l*QS_, nullptr, qkv, nullptr, QS_, DM_);
        attn_kernel<<<dim3(16,HN_,BN_),256,ASMEM>>>(qkv, y);
        tgemm<1><<<g768,256,TGSMEM>>>(y, wo+wdd, bo+l*DM_, x, x, nullptr, DM_, DM_);
        ln_kernel<<<MR_,192>>>(x, ln2w+l*DM_, ln2b+l*DM_, h);
        tgemm<2><<<g3072,256,TGSMEM>>>(h, wf+wff, bfc+(size_t)l*FF_, nullptr, nullptr, f, FF_, DM_);
        tgemm<1><<<g768,256,TGSMEM>>>(f, wp+wff, bpr+l*DM_, x, x, nullptr, DM_, FF_);
    }
    ln_kernel<<<MR_,192>>>(x, lnfw, lnfb, h);
    tgemm<3><<<glm,256,TGSMEM>>>(h, wlm, nullptr, nullptr, out, nullptr, VN_, DM_);
}

// round 10
// speedup vs baseline: 9.4810x; 2.5490x over previous
#include <cuda_runtime.h>
#include <cuda_fp16.h>
#include <math.h>
#include <stdint.h>

#define LN_ 12
#define HN_ 12
#define DM_ 768
#define TM_ 1024
#define BN_ 4
#define VN_ 50257
#define DH_ 64
#define MR_ (BN_*TM_)
#define FF_ (4*DM_)
#define QS_ (3*DM_)
#define DD_ (DM_*DM_)

// ---------------- scratch ----------------
__device__ float g_x  [MR_*DM_];
__device__ float g_bqkv[LN_*QS_];
__device__ __half g_qkv[MR_*QS_];
__device__ __half g_h[MR_*DM_];
__device__ __half g_y[MR_*DM_];
__device__ __half g_f[MR_*FF_];
__device__ __half g_Wqkv[LN_*3*DD_];
__device__ __half g_Wo[LN_*DD_];
__device__ __half g_Wf[LN_*DM_*FF_];
__device__ __half g_Wp[LN_*DM_*FF_];
__device__ __half g_Wlm[(size_t)VN_*DM_];

// ---------------- PTX helpers (base sm_103 target only!) ----------------
__device__ __forceinline__ uint32_t su32(const void* p){
    uint32_t a; asm("{ .reg .u64 t; cvta.to.shared.u64 t, %1; cvt.u32.u64 %0, t; }":"=r"(a):"l"(p)); return a;
}
__device__ __forceinline__ void mma16816(float* c, const uint32_t* a, const uint32_t* b){
    asm volatile("mma.sync.aligned.m16n8k16.row.col.f32.f16.f16.f32 "
        "{%0,%1,%2,%3},{%4,%5,%6,%7},{%8,%9},{%0,%1,%2,%3};"
        : "+f"(c[0]),"+f"(c[1]),"+f"(c[2]),"+f"(c[3])
        : "r"(a[0]),"r"(a[1]),"r"(a[2]),"r"(a[3]),"r"(b[0]),"r"(b[1]));
}
__device__ __forceinline__ void ldsm4(uint32_t* r, uint32_t a){
    asm volatile("ldmatrix.sync.aligned.m8n8.x4.shared.b16 {%0,%1,%2,%3},[%4];"
        :"=r"(r[0]),"=r"(r[1]),"=r"(r[2]),"=r"(r[3]):"r"(a));
}
__device__ __forceinline__ void ldsm4t(uint32_t* r, uint32_t a){
    asm volatile("ldmatrix.sync.aligned.m8n8.x4.trans.shared.b16 {%0,%1,%2,%3},[%4];"
        :"=r"(r[0]),"=r"(r[1]),"=r"(r[2]),"=r"(r[3]):"r"(a));
}
__device__ __forceinline__ void cpa(uint32_t d, const void* g, int vb){
    asm volatile("cp.async.cg.shared.global [%0],[%1],16,%2;"::"r"(d),"l"(g),"r"(vb):"memory");
}
__device__ __forceinline__ void cpcommit(){ asm volatile("cp.async.commit_group;":::"memory"); }
template<int N> __device__ __forceinline__ void cpwait(){ asm volatile("cp.async.wait_group %0;"::"n"(N):"memory"); }

// ---------------- weight transpose + fp16 convert: W[K,N] tile -> o[N,K] ----------------
__device__ __forceinline__ void wtile(const float* __restrict__ W, __half* __restrict__ o, int K, int N){
    __shared__ float t[32][33];
    int k0 = blockIdx.y*32, n0 = blockIdx.x*32;
    #pragma unroll
    for (int i=0;i<4;i++){
        int k = k0 + threadIdx.y + i*8, n = n0 + threadIdx.x;
        t[threadIdx.y+i*8][threadIdx.x] = (n<N) ? W[(size_t)k*N+n] : 0.f;
    }
    __syncthreads();
    #pragma unroll
    for (int i=0;i<4;i++){
        int n = n0 + threadIdx.y + i*8, k = k0 + threadIdx.x;
        if (n<N) o[(size_t)n*K+k] = __float2half(t[threadIdx.x][threadIdx.y+i*8]);
    }
}

__global__ void wconvA(const float* __restrict__ Wq, const float* __restrict__ Wk,
                       const float* __restrict__ Wv, const float* __restrict__ Wo4,
                       __half* __restrict__ wqkv, __half* __restrict__ wo){
    int l = blockIdx.z >> 2, which = blockIdx.z & 3;
    const float* src = which==0?Wq:which==1?Wk:which==2?Wv:Wo4;
    src += (size_t)l*DD_;
    __half* dst = (which<3) ? wqkv + (size_t)l*3*DD_ + (size_t)which*DD_
                            : wo   + (size_t)l*DD_;
    wtile(src, dst, DM_, DM_);
}
__global__ void wconvB(const float* __restrict__ Wfc, const float* __restrict__ Wpr,
                       __half* __restrict__ wf, __half* __restrict__ wp){
    int l = blockIdx.z >> 1;
    if ((blockIdx.z & 1)==0){
        if (blockIdx.x>=96 || blockIdx.y>=24) return;
        wtile(Wfc + (size_t)l*DM_*FF_, wf + (size_t)l*DM_*FF_, DM_, FF_);
    } else {
        if (blockIdx.x>=24 || blockIdx.y>=96) return;
        wtile(Wpr + (size_t)l*DM_*FF_, wp + (size_t)l*DM_*FF_, FF_, DM_);
    }
}
__global__ void wconvLM(const float* __restrict__ Wlm, __half* __restrict__ wlm){
    wtile(Wlm, wlm, DM_, VN_);
}

// ---------------- embedding + bias concat ----------------
__global__ void embed_kernel(const int* __restrict__ idx, const float* __restrict__ wte,
                             const float* __restrict__ wpe, float* __restrict__ x,
                             const float* __restrict__ bq, const float* __restrict__ bk,
                             const float* __restrict__ bv, float* __restrict__ bqkv){
    int row = blockIdx.x;
    float4 a = ((const float4*)(wte + (size_t)idx[row]*DM_))[threadIdx.x];
    float4 p = ((const float4*)(wpe + (size_t)(row&(TM_-1))*DM_))[threadIdx.x];
    a.x+=p.x; a.y+=p.y; a.z+=p.z; a.w+=p.w;
    ((float4*)(x + (size_t)row*DM_))[threadIdx.x] = a;
    if (row < LN_){
        for (int j=threadIdx.x; j<QS_; j+=192){
            float v = (j<DM_) ? bq[row*DM_+j] : (j<2*DM_) ? bk[row*DM_+j-DM_] : bv[row*DM_+j-2*DM_];
            bqkv[row*QS_+j] = v;
        }
    }
}

// ---------------- layernorm -> fp16 (192 threads) ----------------
__global__ void ln_kernel(const float* __restrict__ x, const float* __restrict__ w, const float* __restrict__ b,
                          __half* __restrict__ oh){
    int row = blockIdx.x, tid = threadIdx.x;
    float4 v = ((const float4*)(x + (size_t)row*DM_))[tid];
    float s = v.x+v.y+v.z+v.w;
    float sq = v.x*v.x+v.y*v.y+v.z*v.z+v.w*v.w;
    __shared__ float ss[6], sp[6];
    #pragma unroll
    for (int o=16;o;o>>=1){ s+=__shfl_xor_sync(~0u,s,o); sq+=__shfl_xor_sync(~0u,sq,o); }
    if ((tid&31)==0){ ss[tid>>5]=s; sp[tid>>5]=sq; }
    __syncthreads();
    s=0; sq=0;
    #pragma unroll
    for (int i=0;i<6;i++){ s+=ss[i]; sq+=sp[i]; }
    float mean = s*(1.f/DM_), var = sq*(1.f/DM_)-mean*mean, rstd = rsqrtf(var+1e-5f);
    float4 wv = ((const float4*)w)[tid], bv = ((const float4*)b)[tid];
    __half hh[4];
    hh[0] = __float2half((v.x-mean)*rstd*wv.x+bv.x);
    hh[1] = __float2half((v.y-mean)*rstd*wv.y+bv.y);
    hh[2] = __float2half((v.z-mean)*rstd*wv.z+bv.z);
    hh[3] = __float2half((v.w-mean)*rstd*wv.w+bv.w);
    ((uint2*)(oh + (size_t)row*DM_))[tid] = *(uint2*)hh;
}

// ---------------- HMMA GEMM fp16: C[M,N] = A[M,K] @ B[N,K]^T ----------------
// EPI: 0 bias->fp16, 1 bias+res->f32, 2 bias+gelu->fp16, 3 none->f32
// CTA 128x128x64, 2-stage cp.async, 8 warps (2m x 4n), 2 CTAs/SM. Row stride 144B.
#define STGB   36864u
#define BT_    18432u
#define TGSMEM (2*36864)
template<int EPI>
__global__ void __launch_bounds__(256,2)
tgemm(const __half* __restrict__ A, const __half* __restrict__ B,
      const float* __restrict__ bias, const float* __restrict__ res,
      float* __restrict__ outf, __half* __restrict__ outh,
      int N, int K){
    extern __shared__ char smem[];
    uint32_t sb = su32(smem);
    const int tid = threadIdx.x;
    const int m0 = blockIdx.x*128, n0 = blockIdx.y*128;
    const int NT = K >> 6;

    auto load_tile = [&](int kt){
        uint32_t base = sb + (uint32_t)(kt&1)*STGB;
        #pragma unroll
        for (int i=0;i<4;i++){
            int id = tid + i*256; int r = id>>3, c = id&7;
            cpa(base + (uint32_t)(r*144 + c*16),
                (const char*)(A + (size_t)(m0+r)*K + kt*64) + c*16, 16);
        }
        #pragma unroll
        for (int i=0;i<4;i++){
            int id = tid + i*256; int r = id>>3, c = id&7;
            int vb = (n0+r) < N ? 16 : 0;
            cpa(base + BT_ + (uint32_t)(r*144 + c*16),
                (const char*)(B + (size_t)(n0+r)*K + kt*64) + c*16, vb);
        }
        cpcommit();
    };

    load_tile(0); if (NT>1) load_tile(1);

    const int l = tid & 31;
    const int wid = tid >> 5, wm = wid & 1, wn = wid >> 1;
    const uint32_t aoff = (uint32_t)((wm*64 + (l&7) + ((l>>3)&1)*8)*144 + (l>>4)*16);
    const uint32_t boff = (uint32_t)((wn*32 + (l&7) + (l>>4)*8)*144 + ((l>>3)&1)*16);

    float acc[4][4][4];
    #pragma unroll
    for (int i=0;i<4;i++) for (int j=0;j<4;j++) for (int r=0;r<4;r++) acc[i][j][r]=0.f;

    for (int kt=0; kt<NT; kt++){
        if (kt+2<=NT) cpwait<1>();
        else cpwait<0>();
        __syncthreads();
        uint32_t base = sb + (uint32_t)(kt&1)*STGB;
        #pragma unroll
        for (int ks=0; ks<4; ks++){
            uint32_t af[4][4], bf_[2][4];
            #pragma unroll
            for (int mi=0; mi<4; mi++)
                ldsm4(af[mi], base + aoff + (uint32_t)(mi*16*144 + ks*32));
            #pragma unroll
            for (int nb=0; nb<2; nb++)
                ldsm4(bf_[nb], base + BT_ + boff + (uint32_t)(nb*16*144 + ks*32));
            #pragma unroll
            for (int mi=0; mi<4; mi++)
                #pragma unroll
                for (int ni=0; ni<4; ni++)
                    mma16816(acc[mi][ni], af[mi], &bf_[ni>>1][(ni&1)*2]);
        }
        __syncthreads();
        if (kt+2<NT) load_tile(kt+2);
    }

    const float kg = 0.7978845608028654f;
    #pragma unroll
    for (int mi=0; mi<4; mi++){
        #pragma unroll
        for (int ni=0; ni<4; ni++){
            #pragma unroll
            for (int half_=0; half_<2; half_++){
                int r = m0 + wm*64 + mi*16 + (l>>2) + half_*8;
                int c = n0 + wn*32 + ni*8 + (l&3)*2;
                float v0 = acc[mi][ni][half_*2], v1 = acc[mi][ni][half_*2+1];
                #pragma unroll
                for (int e=0; e<2; e++){
                    int cc = c + e;
                    if (cc < N){
                        float v = e ? v1 : v0;
                        size_t o = (size_t)r*N + cc;
                        if (EPI==0) outh[o] = __float2half(v + bias[cc]);
                        else if (EPI==1) outf[o] = v + bias[cc] + res[o];
                        else if (EPI==2){
                            v += bias[cc];
                            float u = kg*(v + 0.044715f*v*v*v);
                            v = 0.5f*v*(1.f + tanhf(u));
                            outh[o] = __float2half(v);
                        } else outf[o] = v;
                    }
                }
            }
        }
    }
}

// ---------------- tensor-core flash attention (fp16 QK + PV, fp32 softmax) ----------------
// CTA: 128 thr (4 warps), q-tile 64 (16 rows/warp), kv-tile 64. smem stride 72 halfs.
__global__ void __launch_bounds__(128)
attn_kernel(const __half* __restrict__ qkv, __half* __restrict__ y){
    __shared__ __half Qs[64*72], Ks[64*72], Vs[64*72];
    const int tid = threadIdx.x, l = tid & 31, w = tid >> 5;
    const int qb = blockIdx.x, h = blockIdx.y, b = blockIdx.z;
    const __half* qp = qkv + (size_t)(b*TM_ + qb*64)*QS_ + h*DH_;
    const __half* kp = qkv + (size_t)b*TM_*QS_ + DM_   + h*DH_;
    const __half* vp = qkv + (size_t)b*TM_*QS_ + 2*DM_ + h*DH_;
    uint32_t sQ = su32(Qs), sK = su32(Ks), sV = su32(Vs);

    #pragma unroll
    for (int i=0;i<4;i++){
        int id = tid + i*128; int r = id>>3, c = id&7;
        *(uint4*)(Qs + r*72 + c*8) = *(const uint4*)(qp + (size_t)r*QS_ + c*8);
    }
    __syncthreads();
    uint32_t aq[4][4];
    const uint32_t aoff = (uint32_t)((w*16 + (l&7) + ((l>>3)&1)*8)*144 + (l>>4)*16);
    #pragma unroll
    for (int ks=0;ks<4;ks++) ldsm4(aq[ks], sQ + aoff + ks*32);

    float O[8][4];
    #pragma unroll
    for (int j=0;j<8;j++) for (int e=0;e<4;e++) O[j][e]=0.f;
    float m0=-1e30f, m1=-1e30f, l0=0.f, l1=0.f;
    const int row0 = qb*64 + w*16 + (l>>2);

    for (int kt=0; kt<=qb; kt++){
        __syncthreads();
        #pragma unroll
        for (int i=0;i<4;i++){
            int id = tid + i*128; int r = id>>3, c = id&7;
            *(uint4*)(Ks + r*72 + c*8) = *(const uint4*)(kp + (size_t)(kt*64+r)*QS_ + c*8);
            *(uint4*)(Vs + r*72 + c*8) = *(const uint4*)(vp + (size_t)(kt*64+r)*QS_ + c*8);
        }
        __syncthreads();

        float sc[8][4];
        #pragma unroll
        for (int j=0;j<8;j++) for (int e=0;e<4;e++) sc[j][e]=0.f;
        // B-operand pattern (matches tgemm): row=(l&7)+(l>>4)*8, colByte=((l>>3)&1)*16
        const uint32_t boffK = (uint32_t)(((l&7) + (l>>4)*8)*144 + ((l>>3)&1)*16);
        #pragma unroll
        for (int ks=0;ks<4;ks++){
            #pragma unroll
            for (int nb=0;nb<4;nb++){
                uint32_t bk[4];
                ldsm4(bk, sK + boffK + (uint32_t)(nb*16*144 + ks*32));
                mma16816(sc[nb*2],   aq[ks], bk);
                mma16816(sc[nb*2+1], aq[ks], bk+2);
            }
        }
        // scale + causal mask
        #pragma unroll
        for (int j=0;j<8;j++){
            #pragma unroll
            for (int e=0;e<4;e++) sc[j][e] *= 0.125f;
        }
        if (kt==qb){
            #pragma unroll
            for (int j=0;j<8;j++){
                int col = kt*64 + j*8 + (l&3)*2;
                if (col   > row0)   sc[j][0] = -1e30f;
                if (col+1 > row0)   sc[j][1] = -1e30f;
                if (col   > row0+8) sc[j][2] = -1e30f;
                if (col+1 > row0+8) sc[j][3] = -1e30f;
            }
        }
        // online softmax
        float mx0=-1e30f, mx1=-1e30f;
        #pragma unroll
        for (int j=0;j<8;j++){
            mx0 = fmaxf(mx0, fmaxf(sc[j][0], sc[j][1]));
            mx1 = fmaxf(mx1, fmaxf(sc[j][2], sc[j][3]));
        }
        mx0 = fmaxf(mx0, __shfl_xor_sync(~0u, mx0, 1));
        mx0 = fmaxf(mx0, __shfl_xor_sync(~0u, mx0, 2));
        mx1 = fmaxf(mx1, __shfl_xor_sync(~0u, mx1, 1));
        mx1 = fmaxf(mx1, __shfl_xor_sync(~0u, mx1, 2));
        float nm0 = fmaxf(m0, mx0), nm1 = fmaxf(m1, mx1);
        float f0 = __expf(m0-nm0), f1 = __expf(m1-nm1);
        float s0 = 0.f, s1 = 0.f;
        uint32_t ap[4][4];
        #pragma unroll
        for (int j2=0;j2<4;j2++){
            float p00=__expf(sc[2*j2][0]-nm0),   p01=__expf(sc[2*j2][1]-nm0);
            float p02=__expf(sc[2*j2][2]-nm1),   p03=__expf(sc[2*j2][3]-nm1);
            float p10=__expf(sc[2*j2+1][0]-nm0), p11=__expf(sc[2*j2+1][1]-nm0);
            float p12=__expf(sc[2*j2+1][2]-nm1), p13=__expf(sc[2*j2+1][3]-nm1);
            s0 += p00+p01+p10+p11;
            s1 += p02+p03+p12+p13;
            __half2 h0 = __floats2half2_rn(p00,p01), h1 = __floats2half2_rn(p02,p03);
            __half2 h2v = __floats2half2_rn(p10,p11), h3 = __floats2half2_rn(p12,p13);
            ap[j2][0] = *(uint32_t*)&h0;  ap[j2][1] = *(uint32_t*)&h1;
            ap[j2][2] = *(uint32_t*)&h2v; ap[j2][3] = *(uint32_t*)&h3;
        }
        s0 += __shfl_xor_sync(~0u, s0, 1); s0 += __shfl_xor_sync(~0u, s0, 2);
        s1 += __shfl_xor_sync(~0u, s1, 1); s1 += __shfl_xor_sync(~0u, s1, 2);
        l0 = l0*f0 + s0; l1 = l1*f1 + s1; m0 = nm0; m1 = nm1;
        #pragma unroll
        for (int j=0;j<8;j++){ O[j][0]*=f0; O[j][1]*=f0; O[j][2]*=f1; O[j][3]*=f1; }
        // PV: V^T via ldsm trans
        #pragma unroll
        for (int kp2=0;kp2<4;kp2++){
            #pragma unroll
            for (int dv=0;dv<4;dv++){
                uint32_t bv[4];
                ldsm4t(bv, sV + (uint32_t)((kp2*16 + (l&7) + ((l>>3)&1)*8)*144 + dv*32 + (l>>4)*16));
                mma16816(O[dv*2],   ap[kp2], bv);
                mma16816(O[dv*2+1], ap[kp2], bv+2);
            }
        }
    }
    float inv0 = 1.f/l0, inv1 = 1.f/l1;
    size_t r0 = (size_t)(b*TM_ + qb*64 + w*16 + (l>>2));
    #pragma unroll
    for (int j=0;j<8;j++){
        int d = h*DH_ + j*8 + (l&3)*2;
        __half2 o0 = __floats2half2_rn(O[j][0]*inv0, O[j][1]*inv0);
        __half2 o1 = __floats2half2_rn(O[j][2]*inv1, O[j][3]*inv1);
        *(__half2*)(y + r0*DM_ + d)     = o0;
        *(__half2*)(y + (r0+8)*DM_ + d) = o1;
    }
}

// ---------------- launch ----------------
extern "C" void kernel_launch(void* const* d_in, const int* in_sizes, int n_in,
                              void* d_out, int out_size){
    const int*   idx  = (const int*)  d_in[0];
    const float* wte  = (const float*)d_in[1];
    const float* wpe  = (const float*)d_in[2];
    const float* ln1w = (const float*)d_in[3];
    const float* ln1b = (const float*)d_in[4];
    const float* Wq   = (const float*)d_in[5];
    const float* bq   = (const float*)d_in[6];
    const float* Wk   = (const float*)d_in[7];
    const float* bk   = (const float*)d_in[8];
    const float* Wv   = (const float*)d_in[9];
    const float* bv   = (const float*)d_in[10];
    const float* Wo   = (const float*)d_in[11];
    const float* bo   = (const float*)d_in[12];
    const float* ln2w = (const float*)d_in[13];
    const float* ln2b = (const float*)d_in[14];
    const float* Wfc  = (const float*)d_in[15];
    const float* bfc  = (const float*)d_in[16];
    const float* Wpr  = (const float*)d_in[17];
    const float* bpr  = (const float*)d_in[18];
    const float* lnfw = (const float*)d_in[19];
    const float* lnfb = (const float*)d_in[20];
    const float* Wlm  = (const float*)d_in[21];
    float* out = (float*)d_out;

    float *x,*bqkv;
    __half *qkv,*h,*y,*f,*wqkv,*wo,*wf,*wp,*wlm;
    cudaGetSymbolAddress((void**)&x, g_x);
    cudaGetSymbolAddress((void**)&bqkv, g_bqkv);
    cudaGetSymbolAddress((void**)&qkv, g_qkv);
    cudaGetSymbolAddress((void**)&h, g_h);
    cudaGetSymbolAddress((void**)&y, g_y);
    cudaGetSymbolAddress((void**)&f, g_f);
    cudaGetSymbolAddress((void**)&wqkv, g_Wqkv);
    cudaGetSymbolAddress((void**)&wo, g_Wo);
    cudaGetSymbolAddress((void**)&wf, g_Wf);
    cudaGetSymbolAddress((void**)&wp, g_Wp);
    cudaGetSymbolAddress((void**)&wlm, g_Wlm);

    cudaFuncSetAttribute(tgemm<0>, cudaFuncAttributeMaxDynamicSharedMemorySize, TGSMEM);
    cudaFuncSetAttribute(tgemm<1>, cudaFuncAttributeMaxDynamicSharedMemorySize, TGSMEM);
    cudaFuncSetAttribute(tgemm<2>, cudaFuncAttributeMaxDynamicSharedMemorySize, TGSMEM);
    cudaFuncSetAttribute(tgemm<3>, cudaFuncAttributeMaxDynamicSharedMemorySize, TGSMEM);

    // launch order: embed(1), wconvA(2), wconvB(3), wconvLM(4), ln(5), tgemm<0>(6) <- ncu -s 5 -c 1
    embed_kernel<<<MR_, 192>>>(idx, wte, wpe, x, bq, bk, bv, bqkv);
    wconvA<<<dim3(24,24,4*LN_), dim3(32,8)>>>(Wq, Wk, Wv, Wo, wqkv, wo);
    wconvB<<<dim3(96,96,2*LN_), dim3(32,8)>>>(Wfc, Wpr, wf, wp);
    wconvLM<<<dim3((VN_+31)/32, 24), dim3(32,8)>>>(Wlm, wlm);

    dim3 gqkv(32, QS_/128), g768(32, 6), g3072(32, FF_/128), glm(32, (VN_+127)/128);
    for (int l=0; l<LN_; l++){
        size_t wdd = (size_t)l*DD_, wq3 = (size_t)l*3*DD_, wff = (size_t)l*DM_*FF_;
        ln_kernel<<<MR_,192>>>(x, ln1w+l*DM_, ln1b+l*DM_, h);
        tgemm<0><<<gqkv,256,TGSMEM>>>(h, wqkv+wq3, bqkv+l*QS_, nullptr, nullptr, qkv, QS_, DM_);
        attn_kernel<<<dim3(16,HN_,BN_),128>>>(qkv, y);
        tgemm<1><<<g768,256,TGSMEM>>>(y, wo+wdd, bo+l*DM_, x, x, nullptr, DM_, DM_);
        ln_kernel<<<MR_,192>>>(x, ln2w+l*DM_, ln2b+l*DM_, h);
        tgemm<2><<<g3072,256,TGSMEM>>>(h, wf+wff, bfc+(size_t)l*FF_, nullptr, nullptr, f, FF_, DM_);
        tgemm<1><<<g768,256,TGSMEM>>>(f, wp+wff, bpr+l*DM_, x, x, nullptr, DM_, FF_);
    }
    ln_kernel<<<MR_,192>>>(x, lnfw, lnfb, h);
    tgemm<3><<<glm,256,TGSMEM>>>(h, wlm, nullptr, nullptr, out, nullptr, VN_, DM_);
}